// round 9
// baseline (speedup 1.0000x reference)
#include <cuda_runtime.h>
#include <cuda_bf16.h>
#include <stdint.h>
#include <math.h>

// Problem constants
#define VD 16384
#define ED 1024
#define HD 1024
#define H2 2048
#define LD 2
#define BD 128
#define TD 256
#define SD 64
#define TB 32768   // B*T

// ---------------- scratch (__device__ globals; no allocations allowed) -------------
__device__ float g_X [(size_t)TB * HD];
__device__ float g_XG[(size_t)TB * H2];
__device__ float g_XC[(size_t)TB * HD];
__device__ float g_O0[(size_t)TB * HD];
__device__ float g_O1[(size_t)TB * HD];
__device__ float g_h [BD * HD];           // recurrent state fp32
__device__ __nv_bfloat16 g_hb [BD * HD];  // recurrent state bf16 (mma operand)
__device__ __nv_bfloat16 g_RHb[BD * HD];  // r*h bf16 (mma operand)
__device__ float g_U [BD * HD];           // update gate fp32
__device__ float g_sampWT[HD * SD];
__device__ float g_sampB [SD];
__device__ int   g_rowidx[TB];
__device__ unsigned g_barcnt;

__device__ __nv_bfloat16 g_Ab [(size_t)TB * HD];
__device__ __nv_bfloat16 g_Eb [(size_t)VD * ED];
__device__ __nv_bfloat16 g_WbT[(size_t)H2 * HD];

__device__ __forceinline__ float softplusf(float x) {
    return fmaxf(x, 0.f) + log1pf(expf(-fabsf(x)));
}

// ---------------- PTX helpers ----------------
__device__ __forceinline__ uint32_t s2u(const void* p) {
    uint32_t a;
    asm("{ .reg .u64 t; cvta.to.shared.u64 t, %1; cvt.u32.u64 %0, t; }" : "=r"(a) : "l"(p));
    return a;
}
__device__ __forceinline__ void cp16(uint32_t dst, const void* src) {
    asm volatile("cp.async.cg.shared.global [%0], [%1], 16;" :: "r"(dst), "l"(src));
}
#define CP_COMMIT() asm volatile("cp.async.commit_group;" ::: "memory")
#define CP_WAIT(n)  asm volatile("cp.async.wait_group %0;" :: "n"(n) : "memory")

__device__ __forceinline__ void ldmatrix_x4(uint32_t& r0, uint32_t& r1,
                                            uint32_t& r2, uint32_t& r3, uint32_t addr) {
    asm volatile("ldmatrix.sync.aligned.m8n8.x4.shared.b16 {%0,%1,%2,%3}, [%4];"
                 : "=r"(r0), "=r"(r1), "=r"(r2), "=r"(r3) : "r"(addr));
}
__device__ __forceinline__ void mma16816(float* d, const uint32_t* a, const uint32_t* b) {
    asm volatile("mma.sync.aligned.m16n8k16.row.col.f32.bf16.bf16.f32 "
                 "{%0,%1,%2,%3},{%4,%5,%6,%7},{%8,%9},{%0,%1,%2,%3};"
                 : "+f"(d[0]), "+f"(d[1]), "+f"(d[2]), "+f"(d[3])
                 : "r"(a[0]), "r"(a[1]), "r"(a[2]), "r"(a[3]), "r"(b[0]), "r"(b[1]));
}

// software grid barrier
__device__ __forceinline__ void gsync(unsigned target) {
    __syncthreads();
    if (threadIdx.x == 0) {
        __threadfence();
        atomicAdd(&g_barcnt, 1u);
        while (*(volatile unsigned*)&g_barcnt < target) __nanosleep(16);
        __threadfence();
    }
    __syncthreads();
}

// ---------------- tiny helper kernels ----------------
__global__ void k_zero_out(float* p, int n) {
    int i = blockIdx.x * blockDim.x + threadIdx.x;
    if (i < n) p[i] = 0.f;
}
__global__ void k_zero_bar() { g_barcnt = 0u; }

__global__ void k_rowidx(const int* __restrict__ input_data) {
    int r = blockIdx.x * blockDim.x + threadIdx.x;
    if (r < TB) {
        int t = r >> 7, b = r & 127;
        g_rowidx[r] = input_data[b * TD + t];
    }
}

__global__ void k_gather_samp(const int* __restrict__ nce,
                              const float* __restrict__ sw,
                              const float* __restrict__ sb) {
    int s = blockIdx.x;
    int row = nce[s];
    const float* src = sw + (size_t)row * HD;
    for (int k = threadIdx.x; k < HD; k += blockDim.x)
        g_sampWT[k * SD + s] = src[k];
    if (threadIdx.x == 0) g_sampB[s] = sb[row];
}

__global__ void k_f2b(const float* __restrict__ in, __nv_bfloat16* __restrict__ out, int n4) {
    int i = blockIdx.x * blockDim.x + threadIdx.x;
    if (i < n4) {
        float4 v = ((const float4*)in)[i];
        __nv_bfloat162* o = (__nv_bfloat162*)out;
        o[2 * i + 0] = __floats2bfloat162_rn(v.x, v.y);
        o[2 * i + 1] = __floats2bfloat162_rn(v.z, v.w);
    }
}

// fp32 [K,N] -> bf16 transposed [N,K], tiled through smem
__global__ void k_f2bTt(const float* __restrict__ in, __nv_bfloat16* __restrict__ out,
                        int N, int K) {
    __shared__ float tile[32][33];
    const int n0 = blockIdx.x * 32;
    const int k0 = blockIdx.y * 32;
    const int tx = threadIdx.x, ty = threadIdx.y;
    #pragma unroll
    for (int j = 0; j < 4; j++)
        tile[ty + 8 * j][tx] = in[(size_t)(k0 + ty + 8 * j) * N + n0 + tx];
    __syncthreads();
    #pragma unroll
    for (int j = 0; j < 4; j++)
        out[(size_t)(n0 + ty + 8 * j) * K + k0 + tx] =
            __float2bfloat16(tile[tx][ty + 8 * j]);
}

// ---------------- bf16 mma.sync GEMM ----------------
#define LDP 40

template<bool GATHER, bool BIAS>
__global__ __launch_bounds__(256)
void k_mgemm(const __nv_bfloat16* __restrict__ A, const __nv_bfloat16* __restrict__ BT,
             const float* __restrict__ bias, float* __restrict__ C,
             int N, const int* __restrict__ gidx)
{
    __shared__ __align__(16) __nv_bfloat16 sA[2][128 * LDP];
    __shared__ __align__(16) __nv_bfloat16 sB[2][128 * LDP];

    const int tid = threadIdx.x;
    const int rowBase = blockIdx.y * 128;
    const int colBase = blockIdx.x * 128;

    const int lrow = tid & 127;
    const bool isB = tid >= 128;
    const __nv_bfloat16* src;
    if (isB) {
        src = BT + (size_t)(colBase + lrow) * 1024;
    } else {
        size_t ar = GATHER ? (size_t)gidx[rowBase + lrow] : (size_t)(rowBase + lrow);
        src = A + ar * 1024;
    }
    uint32_t dst0 = s2u(isB ? (const void*)&sB[0][lrow * LDP] : (const void*)&sA[0][lrow * LDP]);
    uint32_t dst1 = s2u(isB ? (const void*)&sB[1][lrow * LDP] : (const void*)&sA[1][lrow * LDP]);

    const int wid = tid >> 5, lane = tid & 31;
    const int mb = (wid & 1) * 64;
    const int nb = (wid >> 1) * 32;
    const int arow_l = (lane & 7) + ((lane >> 3) & 1) * 8;
    const int acol_l = (lane >> 4) * 8;
    const int brow_l = (lane & 7) + (lane >> 4) * 8;
    const int bcol_l = ((lane >> 3) & 1) * 8;
    const uint32_t aS0 = s2u(sA[0]), aS1 = s2u(sA[1]);
    const uint32_t bS0 = s2u(sB[0]), bS1 = s2u(sB[1]);

    float acc[4][4][4];
    #pragma unroll
    for (int mt = 0; mt < 4; mt++)
        #pragma unroll
        for (int nt = 0; nt < 4; nt++)
            #pragma unroll
            for (int q = 0; q < 4; q++) acc[mt][nt][q] = 0.f;

    const int S = 32;
    {
        const __nv_bfloat16* p = src;
        #pragma unroll
        for (int c = 0; c < 4; c++) cp16(dst0 + c * 16, p + c * 8);
        CP_COMMIT();
    }

    for (int s = 0; s < S; s++) {
        if (s + 1 < S) {
            uint32_t d = ((s + 1) & 1) ? dst1 : dst0;
            const __nv_bfloat16* p = src + (s + 1) * 32;
            #pragma unroll
            for (int c = 0; c < 4; c++) cp16(d + c * 16, p + c * 8);
            CP_COMMIT();
            CP_WAIT(1);
        } else {
            CP_WAIT(0);
        }
        __syncthreads();

        const uint32_t aS = (s & 1) ? aS1 : aS0;
        const uint32_t bS = (s & 1) ? bS1 : bS0;
        #pragma unroll
        for (int kk = 0; kk < 32; kk += 16) {
            uint32_t af[4][4];
            #pragma unroll
            for (int mt = 0; mt < 4; mt++) {
                uint32_t ad = aS + (uint32_t)(((mb + mt * 16 + arow_l) * LDP) + kk + acol_l) * 2u;
                ldmatrix_x4(af[mt][0], af[mt][1], af[mt][2], af[mt][3], ad);
            }
            uint32_t bf[2][4];
            #pragma unroll
            for (int nt2 = 0; nt2 < 2; nt2++) {
                uint32_t bd = bS + (uint32_t)(((nb + nt2 * 16 + brow_l) * LDP) + kk + bcol_l) * 2u;
                ldmatrix_x4(bf[nt2][0], bf[nt2][1], bf[nt2][2], bf[nt2][3], bd);
            }
            #pragma unroll
            for (int mt = 0; mt < 4; mt++)
                #pragma unroll
                for (int nt = 0; nt < 4; nt++)
                    mma16816(acc[mt][nt], af[mt], &bf[nt >> 1][(nt & 1) * 2]);
        }
        __syncthreads();
    }

    const int erow = lane >> 2;
    const int ecol = (lane & 3) * 2;
    #pragma unroll
    for (int mt = 0; mt < 4; mt++) {
        #pragma unroll
        for (int nt = 0; nt < 4; nt++) {
            int r0 = rowBase + mb + mt * 16 + erow;
            int c0 = colBase + nb + nt * 8 + ecol;
            float b0 = 0.f, b1 = 0.f;
            if (BIAS) { b0 = bias[c0]; b1 = bias[c0 + 1]; }
            float2 v0 = make_float2(acc[mt][nt][0] + b0, acc[mt][nt][1] + b1);
            float2 v1 = make_float2(acc[mt][nt][2] + b0, acc[mt][nt][3] + b1);
            *(float2*)&C[(size_t)r0 * N + c0] = v0;
            *(float2*)&C[(size_t)(r0 + 8) * N + c0] = v1;
        }
    }
}

// ---------------- persistent per-layer MI-GRU recurrence (bf16 tensor-core) ---------
// 64 CTAs x 256 threads. CTA owns gate cols [cta*32,+32) and cand cols [cta*16,+16).
// 3-stage cp.async pipeline (2 chunks in flight) for the h / r*h broadcast;
// epilogue operands prefetched before the mma loop; weights resident in SMEM bf16.
__global__ __launch_bounds__(256)
void k_layer4(const float* __restrict__ Whg, const float* __restrict__ Whc,
              const float* __restrict__ XG, const float* __restrict__ XC,
              const float* __restrict__ ag, const float* __restrict__ b1g,
              const float* __restrict__ b2g, const float* __restrict__ bg,
              const float* __restrict__ ac, const float* __restrict__ b1c,
              const float* __restrict__ b2c, const float* __restrict__ bcv,
              float* __restrict__ outseq, unsigned barBase)
{
    extern __shared__ char smRaw[];
    __nv_bfloat16* Wg  = (__nv_bfloat16*)smRaw;       // [32][1032] bf16 = 66048B
    __nv_bfloat16* Wc  = Wg + 32 * 1032;              // [16][1032] = 33024B
    __nv_bfloat16* stg = Wc + 16 * 1032;              // 3 stages x 128x136 = 104448B

    const int cta = blockIdx.x;                       // 0..63
    const unsigned nCTA = gridDim.x;                  // 64
    const int tid = threadIdx.x;
    const int wid = tid >> 5, lane = tid & 31;
    const int gcol0 = cta * 32, ccol0 = cta * 16;
    const bool isR = (cta < 32);

    // weight slices -> SMEM bf16 ([n][k], stride 1032)
    for (int i = tid; i < 32 * 1024; i += 256) {
        int n = i & 31, k = i >> 5;
        Wg[n * 1032 + k] = __float2bfloat16(Whg[(size_t)k * H2 + gcol0 + n]);
    }
    for (int i = tid; i < 16 * 1024; i += 256) {
        int n = i & 15, k = i >> 4;
        Wc[n * 1032 + k] = __float2bfloat16(Whc[(size_t)k * HD + ccol0 + n]);
    }

    const int arow_l = (lane & 7) + ((lane >> 3) & 1) * 8;
    const int acol_l = (lane >> 4) * 8;
    const int brow_l = (lane & 7) + (lane >> 4) * 8;
    const int bcol_l = ((lane >> 3) & 1) * 8;

    const uint32_t stB = s2u(stg);                 // stage s at stB + s*34816
    const uint32_t wgB = s2u(Wg);
    const uint32_t wcB = s2u(Wc);

    const int erow = lane >> 2;
    const int ecol = (lane & 3) * 2;
    const int r0 = wid * 16 + erow;

    // per-lane gate/cand constants
    float agv[4][2], b1v[4][2], b2v[4][2], bgv[4][2];
    #pragma unroll
    for (int nt = 0; nt < 4; nt++)
        #pragma unroll
        for (int j = 0; j < 2; j++) {
            int col = gcol0 + nt * 8 + ecol + j;
            agv[nt][j] = ag[col]; b1v[nt][j] = b1g[col];
            b2v[nt][j] = b2g[col]; bgv[nt][j] = bg[col];
        }
    float acv[2][2], b1cv[2][2], b2cv[2][2], bcvv[2][2];
    #pragma unroll
    for (int nt = 0; nt < 2; nt++)
        #pragma unroll
        for (int j = 0; j < 2; j++) {
            int col = ccol0 + nt * 8 + ecol + j;
            acv[nt][j] = ac[col]; b1cv[nt][j] = b1c[col];
            b2cv[nt][j] = b2c[col]; bcvv[nt][j] = bcv[col];
        }

    // stage loader mapping: 256 threads, 2 threads/row, 8x16B each
    const int srow = tid & 127;
    const int scb  = (tid >> 7) * 8;
    const uint32_t sdst_off = (uint32_t)(srow * 272 + scb * 16);

    // init h (each CTA zeroes 2048 floats; 64 CTAs cover 128K)
    {
        float4 z = make_float4(0.f, 0.f, 0.f, 0.f);
        __stcg((float4*)(g_h + cta * 2048 + tid * 4), z);
        __stcg((float4*)(g_h + cta * 2048 + 1024 + tid * 4), z);
        uint2 zb = make_uint2(0u, 0u);
        __stcg((uint2*)(g_hb + cta * 2048 + tid * 4), zb);
        __stcg((uint2*)(g_hb + cta * 2048 + 1024 + tid * 4), zb);
    }
    unsigned bar = barBase + 1;
    gsync(bar * nCTA);

    for (int t = 0; t < TD; t++) {
        const float* XGt = XG + (size_t)t * BD * H2;
        const float* XCt = XC + (size_t)t * BD * HD;

        // ================= gate phase: gh = h @ Whg[:,slice32] =================
        {
            // prefetch epilogue operands
            float2 gxv[4][2], hvp[4][2];
            #pragma unroll
            for (int nt = 0; nt < 4; nt++)
                #pragma unroll
                for (int half = 0; half < 2; half++) {
                    int row = r0 + half * 8;
                    int col = gcol0 + nt * 8 + ecol;
                    gxv[nt][half] = __ldcg((const float2*)(XGt + (size_t)row * H2 + col));
                    if (isR)
                        hvp[nt][half] = __ldcg((const float2*)(g_h + (size_t)row * 1024 + col));
                }

            float acc[4][4];
            #pragma unroll
            for (int nt = 0; nt < 4; nt++)
                #pragma unroll
                for (int q = 0; q < 4; q++) acc[nt][q] = 0.f;

            // prologue: chunks 0,1
            #pragma unroll
            for (int p = 0; p < 2; p++) {
                const __nv_bfloat16* src = g_hb + (size_t)srow * 1024 + p * 128 + scb * 8;
                uint32_t dst = stB + (uint32_t)p * 34816u + sdst_off;
                #pragma unroll
                for (int c = 0; c < 8; c++) cp16(dst + c * 16, src + c * 8);
                CP_COMMIT();
            }
            for (int chunk = 0; chunk < 8; chunk++) {
                if (chunk + 2 < 8) {
                    const __nv_bfloat16* src = g_hb + (size_t)srow * 1024 + (chunk + 2) * 128 + scb * 8;
                    uint32_t dst = stB + (uint32_t)((chunk + 2) % 3) * 34816u + sdst_off;
                    #pragma unroll
                    for (int c = 0; c < 8; c++) cp16(dst + c * 16, src + c * 8);
                    CP_COMMIT();
                    CP_WAIT(2);
                } else {
                    CP_WAIT(0);
                }
                __syncthreads();
                uint32_t aB = stB + (uint32_t)(chunk % 3) * 34816u;
                #pragma unroll
                for (int ks = 0; ks < 8; ks++) {
                    int kloc = ks * 16;
                    int kg = chunk * 128 + kloc;
                    uint32_t af[4];
                    ldmatrix_x4(af[0], af[1], af[2], af[3],
                        aB + (uint32_t)((wid * 16 + arow_l) * 272 + (kloc + acol_l) * 2));
                    uint32_t bf[2][4];
                    #pragma unroll
                    for (int g = 0; g < 2; g++)
                        ldmatrix_x4(bf[g][0], bf[g][1], bf[g][2], bf[g][3],
                            wgB + (uint32_t)((g * 16 + brow_l) * 2064 + (kg + bcol_l) * 2));
                    #pragma unroll
                    for (int nt = 0; nt < 4; nt++)
                        mma16816(acc[nt], af, &bf[nt >> 1][(nt & 1) * 2]);
                }
                __syncthreads();
            }

            // epilogue: sigmoid; r-CTAs -> RHb bf16, u-CTAs -> U fp32
            #pragma unroll
            for (int nt = 0; nt < 4; nt++) {
                #pragma unroll
                for (int half = 0; half < 2; half++) {
                    int row = r0 + half * 8;
                    int col = gcol0 + nt * 8 + ecol;
                    float gh0 = acc[nt][half * 2 + 0];
                    float gh1 = acc[nt][half * 2 + 1];
                    float gx0 = gxv[nt][half].x, gx1 = gxv[nt][half].y;
                    float z0 = agv[nt][0] * gx0 * gh0 + b1v[nt][0] * gx0 + b2v[nt][0] * gh0 + bgv[nt][0];
                    float z1 = agv[nt][1] * gx1 * gh1 + b1v[nt][1] * gx1 + b2v[nt][1] * gh1 + bgv[nt][1];
                    float s0 = 1.f / (1.f + expf(-z0));
                    float s1 = 1.f / (1.f + expf(-z1));
                    if (isR) {
                        __nv_bfloat162 p = __floats2bfloat162_rn(s0 * hvp[nt][half].x,
                                                                 s1 * hvp[nt][half].y);
                        __stcg((uint32_t*)(g_RHb + (size_t)row * 1024 + col), *(uint32_t*)&p);
                    } else {
                        __stcg((float2*)(g_U + (size_t)row * 1024 + (col - 1024)),
                               make_float2(s0, s1));
                    }
                }
            }
        }
        bar++; gsync(bar * nCTA);

        // ================= cand phase: ch = (r*h) @ Whc[:,slice16] =================
        {
            float2 cxv[2][2], uvp[2][2], hvp2[2][2];
            #pragma unroll
            for (int nt = 0; nt < 2; nt++)
                #pragma unroll
                for (int half = 0; half < 2; half++) {
                    int row = r0 + half * 8;
                    int col = ccol0 + nt * 8 + ecol;
                    cxv[nt][half]  = __ldcg((const float2*)(XCt + (size_t)row * HD + col));
                    uvp[nt][half]  = __ldcg((const float2*)(g_U + (size_t)row * 1024 + col));
                    hvp2[nt][half] = __ldcg((const float2*)(g_h + (size_t)row * 1024 + col));
                }

            float acc[2][4];
            #pragma unroll
            for (int nt = 0; nt < 2; nt++)
                #pragma unroll
                for (int q = 0; q < 4; q++) acc[nt][q] = 0.f;

            #pragma unroll
            for (int p = 0; p < 2; p++) {
                const __nv_bfloat16* src = g_RHb + (size_t)srow * 1024 + p * 128 + scb * 8;
                uint32_t dst = stB + (uint32_t)p * 34816u + sdst_off;
                #pragma unroll
                for (int c = 0; c < 8; c++) cp16(dst + c * 16, src + c * 8);
                CP_COMMIT();
            }
            for (int chunk = 0; chunk < 8; chunk++) {
                if (chunk + 2 < 8) {
                    const __nv_bfloat16* src = g_RHb + (size_t)srow * 1024 + (chunk + 2) * 128 + scb * 8;
                    uint32_t dst = stB + (uint32_t)((chunk + 2) % 3) * 34816u + sdst_off;
                    #pragma unroll
                    for (int c = 0; c < 8; c++) cp16(dst + c * 16, src + c * 8);
                    CP_COMMIT();
                    CP_WAIT(2);
                } else {
                    CP_WAIT(0);
                }
                __syncthreads();
                uint32_t aB = stB + (uint32_t)(chunk % 3) * 34816u;
                #pragma unroll
                for (int ks = 0; ks < 8; ks++) {
                    int kloc = ks * 16;
                    int kg = chunk * 128 + kloc;
                    uint32_t af[4];
                    ldmatrix_x4(af[0], af[1], af[2], af[3],
                        aB + (uint32_t)((wid * 16 + arow_l) * 272 + (kloc + acol_l) * 2));
                    uint32_t bf[4];
                    ldmatrix_x4(bf[0], bf[1], bf[2], bf[3],
                        wcB + (uint32_t)(brow_l * 2064 + (kg + bcol_l) * 2));
                    mma16816(acc[0], af, &bf[0]);
                    mma16816(acc[1], af, &bf[2]);
                }
                __syncthreads();
            }

            // epilogue: tanh candidate, state update, outputs
            #pragma unroll
            for (int nt = 0; nt < 2; nt++) {
                #pragma unroll
                for (int half = 0; half < 2; half++) {
                    int row = r0 + half * 8;
                    int col = ccol0 + nt * 8 + ecol;
                    float ch0 = acc[nt][half * 2 + 0];
                    float ch1 = acc[nt][half * 2 + 1];
                    float cx0 = cxv[nt][half].x, cx1 = cxv[nt][half].y;
                    float z0 = acv[nt][0] * cx0 * ch0 + b1cv[nt][0] * cx0 + b2cv[nt][0] * ch0 + bcvv[nt][0];
                    float z1 = acv[nt][1] * cx1 * ch1 + b1cv[nt][1] * cx1 + b2cv[nt][1] * ch1 + bcvv[nt][1];
                    float c0 = tanhf(z0), c1 = tanhf(z1);
                    float hn0 = uvp[nt][half].x * hvp2[nt][half].x + (1.f - uvp[nt][half].x) * c0;
                    float hn1 = uvp[nt][half].y * hvp2[nt][half].y + (1.f - uvp[nt][half].y) * c1;
                    __stcg((float2*)(g_h + (size_t)row * 1024 + col), make_float2(hn0, hn1));
                    __nv_bfloat162 p = __floats2bfloat162_rn(hn0, hn1);
                    __stcg((uint32_t*)(g_hb + (size_t)row * 1024 + col), *(uint32_t*)&p);
                    *(float2*)(outseq + (size_t)t * BD * HD + (size_t)row * HD + col) =
                        make_float2(hn0, hn1);
                }
            }
        }
        bar++; gsync(bar * nCTA);
    }
}

// ---------------- NCE sampled logits ----------------
__global__ __launch_bounds__(256)
void k_nce_samp(float* __restrict__ outsum)
{
    __shared__ float As[8][132];
    __shared__ float Bs[8][64];
    __shared__ float red[256];
    const int tid = threadIdx.x;
    const int rowBase = blockIdx.x * 128;

    const int arow = tid >> 1;
    const int acol = (tid & 1) << 2;
    int gi = rowBase + arow;
    size_t aoff = (size_t)((gi & 255) * BD + (gi >> 8)) * HD;

    const int brow = tid >> 5;
    const int bcl  = (tid & 31) << 1;
    const int ty = tid >> 4;
    const int tx = tid & 15;

    float acc[8][4];
    #pragma unroll
    for (int i = 0; i < 8; i++)
        #pragma unroll
        for (int j = 0; j < 4; j++) acc[i][j] = 0.f;

    for (int k0 = 0; k0 < HD; k0 += 8) {
        float4 av = *(const float4*)(g_O1 + aoff + k0 + acol);
        As[acol + 0][arow] = av.x;
        As[acol + 1][arow] = av.y;
        As[acol + 2][arow] = av.z;
        As[acol + 3][arow] = av.w;
        float2 bw = *(const float2*)(g_sampWT + (size_t)(k0 + brow) * SD + bcl);
        Bs[brow][bcl]     = bw.x;
        Bs[brow][bcl + 1] = bw.y;
        __syncthreads();
        #pragma unroll
        for (int k = 0; k < 8; k++) {
            float ar[8], br[4];
            *(float4*)&ar[0] = *(const float4*)&As[k][ty * 8];
            *(float4*)&ar[4] = *(const float4*)&As[k][ty * 8 + 4];
            *(float4*)&br[0] = *(const float4*)&Bs[k][tx * 4];
            #pragma unroll
            for (int i = 0; i < 8; i++)
                #pragma unroll
                for (int j = 0; j < 4; j++)
                    acc[i][j] += ar[i] * br[j];
        }
        __syncthreads();
    }

    float s = 0.f;
    #pragma unroll
    for (int j = 0; j < 4; j++) {
        float sbv = g_sampB[tx * 4 + j];
        #pragma unroll
        for (int i = 0; i < 8; i++)
            s += softplusf(acc[i][j] + sbv);
    }
    red[tid] = s;
    __syncthreads();
    for (int o = 128; o > 0; o >>= 1) {
        if (tid < o) red[tid] += red[tid + o];
        __syncthreads();
    }
    if (tid == 0) atomicAdd(outsum, red[0] * (1.f / 32768.f));
}

__global__ __launch_bounds__(256)
void k_nce_true(const int* __restrict__ targets, const float* __restrict__ sw,
                const float* __restrict__ sb, float* __restrict__ outsum)
{
    __shared__ float red[8];
    const int warp = threadIdx.x >> 5;
    const int lane = threadIdx.x & 31;
    const int i = blockIdx.x * 8 + warp;
    const int label = targets[i];
    const float* orow = g_O1 + (size_t)((i & 255) * BD + (i >> 8)) * HD;
    const float* wrow = sw + (size_t)label * HD;

    float s = 0.f;
    #pragma unroll
    for (int k0 = 0; k0 < HD; k0 += 128) {
        float4 a = *(const float4*)(orow + k0 + lane * 4);
        float4 w = *(const float4*)(wrow + k0 + lane * 4);
        s += a.x * w.x + a.y * w.y + a.z * w.z + a.w * w.w;
    }
    #pragma unroll
    for (int o = 16; o > 0; o >>= 1) s += __shfl_xor_sync(0xffffffffu, s, o);
    if (lane == 0) {
        float logit = s + sb[label];
        red[warp] = softplusf(-logit);
    }
    __syncthreads();
    if (threadIdx.x == 0) {
        float t = 0.f;
        #pragma unroll
        for (int w = 0; w < 8; w++) t += red[w];
        atomicAdd(outsum, t * (1.f / 32768.f));
    }
}

// ---------------- launch ----------------
extern "C" void kernel_launch(void* const* d_in, const int* in_sizes, int n_in,
                              void* d_out, int out_size)
{
    const int*   input_data = (const int*)  d_in[0];
    const int*   targets    = (const int*)  d_in[1];
    const int*   nce        = (const int*)  d_in[2];
    const float* embedding  = (const float*)d_in[3];
    const float* win        = (const float*)d_in[4];
    const float* bin_       = (const float*)d_in[5];
    const float* Wxg        = (const float*)d_in[6];
    const float* Whg        = (const float*)d_in[7];
    const float* ag         = (const float*)d_in[8];
    const float* b1g        = (const float*)d_in[9];
    const float* b2g        = (const float*)d_in[10];
    const float* bg         = (const float*)d_in[11];
    const float* Wxc        = (const float*)d_in[12];
    const float* Whc        = (const float*)d_in[13];
    const float* ac         = (const float*)d_in[14];
    const float* b1c        = (const float*)d_in[15];
    const float* b2c        = (const float*)d_in[16];
    const float* bc         = (const float*)d_in[17];
    const float* softmax_w  = (const float*)d_in[18];
    const float* softmax_b  = (const float*)d_in[19];
    float* out = (float*)d_out;

    float *pX, *pXG, *pXC, *pO0, *pO1;
    int* pidx;
    __nv_bfloat16 *pAb, *pEb, *pWbT;
    cudaGetSymbolAddress((void**)&pX,  g_X);
    cudaGetSymbolAddress((void**)&pXG, g_XG);
    cudaGetSymbolAddress((void**)&pXC, g_XC);
    cudaGetSymbolAddress((void**)&pO0, g_O0);
    cudaGetSymbolAddress((void**)&pO1, g_O1);
    cudaGetSymbolAddress((void**)&pidx, g_rowidx);
    cudaGetSymbolAddress((void**)&pAb, g_Ab);
    cudaGetSymbolAddress((void**)&pEb, g_Eb);
    cudaGetSymbolAddress((void**)&pWbT, g_WbT);

    // dynamic smem: Wg 66048 + Wc 33024 + 3 stages x 34816 = 203520 bytes
    cudaFuncSetAttribute(k_layer4,
                         cudaFuncAttributeMaxDynamicSharedMemorySize, 203520);

    k_zero_out<<<1, 32>>>(out, out_size);
    k_zero_bar<<<1, 1>>>();
    k_rowidx<<<TB / 256, 256>>>(input_data);
    k_gather_samp<<<SD, 256>>>(nce, softmax_w, softmax_b);

    // embedding table -> bf16; win -> bf16 transposed
    k_f2b<<<(VD * ED / 4) / 256, 256>>>(embedding, pEb, VD * ED / 4);
    k_f2bTt<<<dim3(HD / 32, ED / 32), dim3(32, 8)>>>(win, pWbT, HD, ED);

    // X = gather(Eb) @ win + bin_
    k_mgemm<true, true><<<dim3(HD / 128, TB / 128), 256>>>(
        pEb, pWbT, bin_, pX, HD, pidx);

    const float* inpF = pX;
    float* outb[2] = {pO0, pO1};
    for (int l = 0; l < LD; l++) {
        // A operand -> bf16
        k_f2b<<<((size_t)TB * HD / 4) / 256, 256>>>(inpF, pAb, TB * HD / 4);

        // XG = A @ Wxg[l]
        k_f2bTt<<<dim3(H2 / 32, HD / 32), dim3(32, 8)>>>(
            Wxg + (size_t)l * HD * H2, pWbT, H2, HD);
        k_mgemm<false, false><<<dim3(H2 / 128, TB / 128), 256>>>(
            pAb, pWbT, nullptr, pXG, H2, nullptr);

        // XC = A @ Wxc[l]
        k_f2bTt<<<dim3(HD / 32, HD / 32), dim3(32, 8)>>>(
            Wxc + (size_t)l * HD * HD, pWbT, HD, HD);
        k_mgemm<false, false><<<dim3(HD / 128, TB / 128), 256>>>(
            pAb, pWbT, nullptr, pXC, HD, nullptr);

        // persistent tensor-core recurrence (64 fat CTAs)
        unsigned barBase = (unsigned)l * (1u + 2u * TD);
        k_layer4<<<64, 256, 203520>>>(
            Whg + (size_t)l * HD * H2, Whc + (size_t)l * HD * HD,
            pXG, pXC,
            ag  + (size_t)l * H2, b1g + (size_t)l * H2,
            b2g + (size_t)l * H2, bg  + (size_t)l * H2,
            ac  + (size_t)l * HD, b1c + (size_t)l * HD,
            b2c + (size_t)l * HD, bc  + (size_t)l * HD,
            outb[l], barBase);
        inpF = outb[l];
    }

    k_nce_true<<<TB / 8, 256>>>(targets, softmax_w, softmax_b, out);
    k_nce_samp<<<TB / 128, 256>>>(out);
}

// round 10
// speedup vs baseline: 1.0180x; 1.0180x over previous
#include <cuda_runtime.h>
#include <cuda_bf16.h>
#include <stdint.h>
#include <math.h>

// Problem constants
#define VD 16384
#define ED 1024
#define HD 1024
#define H2 2048
#define LD 2
#define BD 128
#define TD 256
#define SD 64
#define TB 32768   // B*T

// ---------------- scratch (__device__ globals; no allocations allowed) -------------
__device__ float g_X [(size_t)TB * HD];
__device__ float g_XG[(size_t)TB * H2];
__device__ float g_XC[(size_t)TB * HD];
__device__ float g_O0[(size_t)TB * HD];
__device__ float g_O1[(size_t)TB * HD];
// double-buffered recurrent state (parity = t & 1)
__device__ float g_h [2 * BD * HD];
__device__ __nv_bfloat16 g_hb [2 * BD * HD];
__device__ __nv_bfloat16 g_RHb[2 * BD * HD];
__device__ float g_U [2 * BD * HD];
__device__ float g_sampWT[HD * SD];
__device__ float g_sampB [SD];
__device__ int   g_rowidx[TB];
__device__ unsigned g_barcnt;
// per-chunk producer counters (monotonic across steps and layers)
__device__ unsigned g_hcnt[8];
__device__ unsigned g_rhcnt[8];
__device__ unsigned g_ucnt[8];

__device__ __nv_bfloat16 g_Ab [(size_t)TB * HD];
__device__ __nv_bfloat16 g_Eb [(size_t)VD * ED];
__device__ __nv_bfloat16 g_WbT[(size_t)H2 * HD];

__device__ __forceinline__ float softplusf(float x) {
    return fmaxf(x, 0.f) + log1pf(expf(-fabsf(x)));
}

// ---------------- PTX helpers ----------------
__device__ __forceinline__ uint32_t s2u(const void* p) {
    uint32_t a;
    asm("{ .reg .u64 t; cvta.to.shared.u64 t, %1; cvt.u32.u64 %0, t; }" : "=r"(a) : "l"(p));
    return a;
}
__device__ __forceinline__ void cp16(uint32_t dst, const void* src) {
    asm volatile("cp.async.cg.shared.global [%0], [%1], 16;" :: "r"(dst), "l"(src));
}
#define CP_COMMIT() asm volatile("cp.async.commit_group;" ::: "memory")
#define CP_WAIT(n)  asm volatile("cp.async.wait_group %0;" :: "n"(n) : "memory")

__device__ __forceinline__ void ldmatrix_x4(uint32_t& r0, uint32_t& r1,
                                            uint32_t& r2, uint32_t& r3, uint32_t addr) {
    asm volatile("ldmatrix.sync.aligned.m8n8.x4.shared.b16 {%0,%1,%2,%3}, [%4];"
                 : "=r"(r0), "=r"(r1), "=r"(r2), "=r"(r3) : "r"(addr));
}
__device__ __forceinline__ void ldmatrix_x2(uint32_t& r0, uint32_t& r1, uint32_t addr) {
    asm volatile("ldmatrix.sync.aligned.m8n8.x2.shared.b16 {%0,%1}, [%2];"
                 : "=r"(r0), "=r"(r1) : "r"(addr));
}
__device__ __forceinline__ void mma16816(float* d, const uint32_t* a, const uint32_t* b) {
    asm volatile("mma.sync.aligned.m16n8k16.row.col.f32.bf16.bf16.f32 "
                 "{%0,%1,%2,%3},{%4,%5,%6,%7},{%8,%9},{%0,%1,%2,%3};"
                 : "+f"(d[0]), "+f"(d[1]), "+f"(d[2]), "+f"(d[3])
                 : "r"(a[0]), "r"(a[1]), "r"(a[2]), "r"(a[3]), "r"(b[0]), "r"(b[1]));
}

// acquire-poll on a monotonic counter
__device__ __forceinline__ void waitcnt(const unsigned* p, unsigned target) {
    unsigned v;
    asm volatile("ld.acquire.gpu.global.u32 %0, [%1];" : "=r"(v) : "l"(p) : "memory");
    while ((int)(v - target) < 0) {
        __nanosleep(20);
        asm volatile("ld.acquire.gpu.global.u32 %0, [%1];" : "=r"(v) : "l"(p) : "memory");
    }
}
// release-increment (call from ONE thread after __syncthreads())
__device__ __forceinline__ void bumpcnt(unsigned* p) {
    asm volatile("red.release.gpu.global.add.u32 [%0], 1;" :: "l"(p) : "memory");
}

// software grid barrier (init only)
__device__ __forceinline__ void gsync(unsigned target) {
    __syncthreads();
    if (threadIdx.x == 0) {
        __threadfence();
        atomicAdd(&g_barcnt, 1u);
        while (*(volatile unsigned*)&g_barcnt < target) __nanosleep(16);
        __threadfence();
    }
    __syncthreads();
}

// ---------------- tiny helper kernels ----------------
__global__ void k_zero_out(float* p, int n) {
    int i = blockIdx.x * blockDim.x + threadIdx.x;
    if (i < n) p[i] = 0.f;
}
__global__ void k_zero_sync() {
    g_barcnt = 0u;
    if (threadIdx.x < 8) {
        g_hcnt[threadIdx.x] = 0u;
        g_rhcnt[threadIdx.x] = 0u;
        g_ucnt[threadIdx.x] = 0u;
    }
}

__global__ void k_rowidx(const int* __restrict__ input_data) {
    int r = blockIdx.x * blockDim.x + threadIdx.x;
    if (r < TB) {
        int t = r >> 7, b = r & 127;
        g_rowidx[r] = input_data[b * TD + t];
    }
}

__global__ void k_gather_samp(const int* __restrict__ nce,
                              const float* __restrict__ sw,
                              const float* __restrict__ sb) {
    int s = blockIdx.x;
    int row = nce[s];
    const float* src = sw + (size_t)row * HD;
    for (int k = threadIdx.x; k < HD; k += blockDim.x)
        g_sampWT[k * SD + s] = src[k];
    if (threadIdx.x == 0) g_sampB[s] = sb[row];
}

__global__ void k_f2b(const float* __restrict__ in, __nv_bfloat16* __restrict__ out, int n4) {
    int i = blockIdx.x * blockDim.x + threadIdx.x;
    if (i < n4) {
        float4 v = ((const float4*)in)[i];
        __nv_bfloat162* o = (__nv_bfloat162*)out;
        o[2 * i + 0] = __floats2bfloat162_rn(v.x, v.y);
        o[2 * i + 1] = __floats2bfloat162_rn(v.z, v.w);
    }
}

__global__ void k_f2bTt(const float* __restrict__ in, __nv_bfloat16* __restrict__ out,
                        int N, int K) {
    __shared__ float tile[32][33];
    const int n0 = blockIdx.x * 32;
    const int k0 = blockIdx.y * 32;
    const int tx = threadIdx.x, ty = threadIdx.y;
    #pragma unroll
    for (int j = 0; j < 4; j++)
        tile[ty + 8 * j][tx] = in[(size_t)(k0 + ty + 8 * j) * N + n0 + tx];
    __syncthreads();
    #pragma unroll
    for (int j = 0; j < 4; j++)
        out[(size_t)(n0 + ty + 8 * j) * K + k0 + tx] =
            __float2bfloat16(tile[tx][ty + 8 * j]);
}

// ---------------- bf16 mma.sync GEMM ----------------
#define LDP 40

template<bool GATHER, bool BIAS>
__global__ __launch_bounds__(256)
void k_mgemm(const __nv_bfloat16* __restrict__ A, const __nv_bfloat16* __restrict__ BT,
             const float* __restrict__ bias, float* __restrict__ C,
             int N, const int* __restrict__ gidx)
{
    __shared__ __align__(16) __nv_bfloat16 sA[2][128 * LDP];
    __shared__ __align__(16) __nv_bfloat16 sB[2][128 * LDP];

    const int tid = threadIdx.x;
    const int rowBase = blockIdx.y * 128;
    const int colBase = blockIdx.x * 128;

    const int lrow = tid & 127;
    const bool isB = tid >= 128;
    const __nv_bfloat16* src;
    if (isB) {
        src = BT + (size_t)(colBase + lrow) * 1024;
    } else {
        size_t ar = GATHER ? (size_t)gidx[rowBase + lrow] : (size_t)(rowBase + lrow);
        src = A + ar * 1024;
    }
    uint32_t dst0 = s2u(isB ? (const void*)&sB[0][lrow * LDP] : (const void*)&sA[0][lrow * LDP]);
    uint32_t dst1 = s2u(isB ? (const void*)&sB[1][lrow * LDP] : (const void*)&sA[1][lrow * LDP]);

    const int wid = tid >> 5, lane = tid & 31;
    const int mb = (wid & 1) * 64;
    const int nb = (wid >> 1) * 32;
    const int arow_l = (lane & 7) + ((lane >> 3) & 1) * 8;
    const int acol_l = (lane >> 4) * 8;
    const int brow_l = (lane & 7) + (lane >> 4) * 8;
    const int bcol_l = ((lane >> 3) & 1) * 8;
    const uint32_t aS0 = s2u(sA[0]), aS1 = s2u(sA[1]);
    const uint32_t bS0 = s2u(sB[0]), bS1 = s2u(sB[1]);

    float acc[4][4][4];
    #pragma unroll
    for (int mt = 0; mt < 4; mt++)
        #pragma unroll
        for (int nt = 0; nt < 4; nt++)
            #pragma unroll
            for (int q = 0; q < 4; q++) acc[mt][nt][q] = 0.f;

    const int S = 32;
    {
        const __nv_bfloat16* p = src;
        #pragma unroll
        for (int c = 0; c < 4; c++) cp16(dst0 + c * 16, p + c * 8);
        CP_COMMIT();
    }

    for (int s = 0; s < S; s++) {
        if (s + 1 < S) {
            uint32_t d = ((s + 1) & 1) ? dst1 : dst0;
            const __nv_bfloat16* p = src + (s + 1) * 32;
            #pragma unroll
            for (int c = 0; c < 4; c++) cp16(d + c * 16, p + c * 8);
            CP_COMMIT();
            CP_WAIT(1);
        } else {
            CP_WAIT(0);
        }
        __syncthreads();

        const uint32_t aS = (s & 1) ? aS1 : aS0;
        const uint32_t bS = (s & 1) ? bS1 : bS0;
        #pragma unroll
        for (int kk = 0; kk < 32; kk += 16) {
            uint32_t af[4][4];
            #pragma unroll
            for (int mt = 0; mt < 4; mt++) {
                uint32_t ad = aS + (uint32_t)(((mb + mt * 16 + arow_l) * LDP) + kk + acol_l) * 2u;
                ldmatrix_x4(af[mt][0], af[mt][1], af[mt][2], af[mt][3], ad);
            }
            uint32_t bf[2][4];
            #pragma unroll
            for (int nt2 = 0; nt2 < 2; nt2++) {
                uint32_t bd = bS + (uint32_t)(((nb + nt2 * 16 + brow_l) * LDP) + kk + bcol_l) * 2u;
                ldmatrix_x4(bf[nt2][0], bf[nt2][1], bf[nt2][2], bf[nt2][3], bd);
            }
            #pragma unroll
            for (int mt = 0; mt < 4; mt++)
                #pragma unroll
                for (int nt = 0; nt < 4; nt++)
                    mma16816(acc[mt][nt], af[mt], &bf[nt >> 1][(nt & 1) * 2]);
        }
        __syncthreads();
    }

    const int erow = lane >> 2;
    const int ecol = (lane & 3) * 2;
    #pragma unroll
    for (int mt = 0; mt < 4; mt++) {
        #pragma unroll
        for (int nt = 0; nt < 4; nt++) {
            int r0 = rowBase + mb + mt * 16 + erow;
            int c0 = colBase + nb + nt * 8 + ecol;
            float b0 = 0.f, b1 = 0.f;
            if (BIAS) { b0 = bias[c0]; b1 = bias[c0 + 1]; }
            float2 v0 = make_float2(acc[mt][nt][0] + b0, acc[mt][nt][1] + b1);
            float2 v1 = make_float2(acc[mt][nt][2] + b0, acc[mt][nt][3] + b1);
            *(float2*)&C[(size_t)r0 * N + c0] = v0;
            *(float2*)&C[(size_t)(r0 + 8) * N + c0] = v1;
        }
    }
}

// ---------------- persistent per-layer MI-GRU recurrence (bf16 tensor-core) ---------
// 128 CTAs x 256 threads. CTA owns gate cols [cta*16,+16) and cand cols [cta*8,+8).
// NO per-step grid barrier: per-chunk producer counters with acquire/release, state
// double-buffered by step parity. 4-stage cp.async pipeline; weights in SMEM bf16.
__global__ __launch_bounds__(256)
void k_layer5(const float* __restrict__ Whg, const float* __restrict__ Whc,
              const float* __restrict__ XG, const float* __restrict__ XC,
              const float* __restrict__ ag, const float* __restrict__ b1g,
              const float* __restrict__ b2g, const float* __restrict__ bg,
              const float* __restrict__ ac, const float* __restrict__ b1c,
              const float* __restrict__ b2c, const float* __restrict__ bcv,
              float* __restrict__ outseq,
              unsigned gsTarget, unsigned hB, unsigned rB)
{
    extern __shared__ char smRaw[];
    __nv_bfloat16* Wg  = (__nv_bfloat16*)smRaw;       // [16][1032] bf16 = 33024B
    __nv_bfloat16* Wc  = Wg + 16 * 1032;              // [8][1032]  = 16512B
    __nv_bfloat16* stg = Wc + 8 * 1032;               // 4 stages x 128x136 = 139264B

    const int cta = blockIdx.x;
    const int tid = threadIdx.x;
    const int wid = tid >> 5, lane = tid & 31;
    const int gcol0 = cta * 16, ccol0 = cta * 8;
    const bool isR = (cta < 64);
    const int gchunk = isR ? (cta >> 3) : ((cta - 64) >> 3);  // RH or U chunk produced
    const int cchunk = cta >> 4;                              // h chunk produced

    // weight slices -> SMEM bf16
    for (int i = tid; i < 16 * 1024; i += 256) {
        int n = i & 15, k = i >> 4;
        Wg[n * 1032 + k] = __float2bfloat16(Whg[(size_t)k * H2 + gcol0 + n]);
    }
    for (int i = tid; i < 8 * 1024; i += 256) {
        int n = i & 7, k = i >> 3;
        Wc[n * 1032 + k] = __float2bfloat16(Whc[(size_t)k * HD + ccol0 + n]);
    }

    const int arow_l = (lane & 7) + ((lane >> 3) & 1) * 8;
    const int acol_l = (lane >> 4) * 8;
    const int brow_l = (lane & 7) + (lane >> 4) * 8;
    const int bcol_l = ((lane >> 3) & 1) * 8;
    const int l16 = lane & 15;

    const uint32_t stB = s2u(stg);
    const uint32_t wgB = s2u(Wg);
    const uint32_t wcB = s2u(Wc);

    const int erow = lane >> 2;
    const int ecol = (lane & 3) * 2;
    const int r0 = wid * 16 + erow;

    float agv[2][2], b1v[2][2], b2v[2][2], bgv[2][2];
    #pragma unroll
    for (int nt = 0; nt < 2; nt++)
        #pragma unroll
        for (int j = 0; j < 2; j++) {
            int col = gcol0 + nt * 8 + ecol + j;
            agv[nt][j] = ag[col]; b1v[nt][j] = b1g[col];
            b2v[nt][j] = b2g[col]; bgv[nt][j] = bg[col];
        }
    float acv[2], b1cv[2], b2cv[2], bcvv[2];
    #pragma unroll
    for (int j = 0; j < 2; j++) {
        int col = ccol0 + ecol + j;
        acv[j] = ac[col]; b1cv[j] = b1c[col];
        b2cv[j] = b2c[col]; bcvv[j] = bcv[col];
    }

    const int srow = tid & 127;
    const int scb  = (tid >> 7) * 8;
    const uint32_t sdst_off = (uint32_t)(srow * 272 + scb * 16);

    // init h into buffer 0
    {
        float4 z = make_float4(0.f, 0.f, 0.f, 0.f);
        __stcg((float4*)(g_h + cta * 1024 + tid * 4), z);
        uint2 zb = make_uint2(0u, 0u);
        __stcg((uint2*)(g_hb + cta * 1024 + tid * 4), zb);
    }
    gsync(gsTarget);

    for (int t = 0; t < TD; t++) {
        const float* XGt = XG + (size_t)t * BD * H2;
        const float* XCt = XC + (size_t)t * BD * HD;
        const int bi = t & 1;
        const int bo = bi ^ 1;
        const __nv_bfloat16* hbIn = g_hb + bi * (BD * HD);
        const float* hIn = g_h + bi * (BD * HD);
        __nv_bfloat16* rhOut = g_RHb + bi * (BD * HD);
        float* uOut = g_U + bi * (BD * HD);
        const unsigned hT = hB + 16u * (unsigned)t;      // h chunk target for step t
        const unsigned rT = rB + 8u * (unsigned)(t + 1); // RH/U target for step t

        // ================= gate phase =================
        {
            // wait own h chunk (for r-CTA epilogue h read), then prefetch
            if (t > 0) waitcnt(&g_hcnt[cta >> 3 > 7 ? 7 : (gcol0 >> 7) < 8 ? (gcol0 >> 7) : 7], hT);
            float2 gxv[2][2], hvp[2][2];
            #pragma unroll
            for (int nt = 0; nt < 2; nt++)
                #pragma unroll
                for (int half = 0; half < 2; half++) {
                    int row = r0 + half * 8;
                    int col = gcol0 + nt * 8 + ecol;
                    gxv[nt][half] = __ldcg((const float2*)(XGt + (size_t)row * H2 + col));
                    if (isR)
                        hvp[nt][half] = __ldcg((const float2*)(hIn + (size_t)row * 1024 + col));
                }

            float acc[2][4];
            #pragma unroll
            for (int nt = 0; nt < 2; nt++)
                #pragma unroll
                for (int q = 0; q < 4; q++) acc[nt][q] = 0.f;

            // prologue: chunks 0..2 (wait then issue)
            #pragma unroll
            for (int p = 0; p < 3; p++) {
                if (t > 0) waitcnt(&g_hcnt[p], hT);
                const __nv_bfloat16* src = hbIn + (size_t)srow * 1024 + p * 128 + scb * 8;
                uint32_t dst = stB + (uint32_t)p * 34816u + sdst_off;
                #pragma unroll
                for (int c = 0; c < 8; c++) cp16(dst + c * 16, src + c * 8);
                CP_COMMIT();
            }
            for (int chunk = 0; chunk < 8; chunk++) {
                if (chunk < 5) {
                    if (t > 0) waitcnt(&g_hcnt[chunk + 3], hT);
                    const __nv_bfloat16* src = hbIn + (size_t)srow * 1024 + (chunk + 3) * 128 + scb * 8;
                    uint32_t dst = stB + (uint32_t)((chunk + 3) & 3) * 34816u + sdst_off;
                    #pragma unroll
                    for (int c = 0; c < 8; c++) cp16(dst + c * 16, src + c * 8);
                    CP_COMMIT();
                    CP_WAIT(3);
                } else {
                    CP_WAIT(0);
                }
                __syncthreads();
                uint32_t aB = stB + (uint32_t)(chunk & 3) * 34816u;
                #pragma unroll
                for (int ks = 0; ks < 8; ks++) {
                    int kloc = ks * 16;
                    int kg = chunk * 128 + kloc;
                    uint32_t af[4];
                    ldmatrix_x4(af[0], af[1], af[2], af[3],
                        aB + (uint32_t)((wid * 16 + arow_l) * 272 + (kloc + acol_l) * 2));
                    uint32_t bf[4];
                    ldmatrix_x4(bf[0], bf[1], bf[2], bf[3],
                        wgB + (uint32_t)(brow_l * 2064 + (kg + bcol_l) * 2));
                    mma16816(acc[0], af, &bf[0]);
                    mma16816(acc[1], af, &bf[2]);
                }
                __syncthreads();
            }

            #pragma unroll
            for (int nt = 0; nt < 2; nt++) {
                #pragma unroll
                for (int half = 0; half < 2; half++) {
                    int row = r0 + half * 8;
                    int col = gcol0 + nt * 8 + ecol;
                    float gh0 = acc[nt][half * 2 + 0];
                    float gh1 = acc[nt][half * 2 + 1];
                    float gx0 = gxv[nt][half].x, gx1 = gxv[nt][half].y;
                    float z0 = agv[nt][0] * gx0 * gh0 + b1v[nt][0] * gx0 + b2v[nt][0] * gh0 + bgv[nt][0];
                    float z1 = agv[nt][1] * gx1 * gh1 + b1v[nt][1] * gx1 + b2v[nt][1] * gh1 + bgv[nt][1];
                    float s0 = 1.f / (1.f + expf(-z0));
                    float s1 = 1.f / (1.f + expf(-z1));
                    if (isR) {
                        __nv_bfloat162 p = __floats2bfloat162_rn(s0 * hvp[nt][half].x,
                                                                 s1 * hvp[nt][half].y);
                        __stcg((uint32_t*)(rhOut + (size_t)row * 1024 + col), *(uint32_t*)&p);
                    } else {
                        __stcg((float2*)(uOut + (size_t)row * 1024 + (col - 1024)),
                               make_float2(s0, s1));
                    }
                }
            }
            __syncthreads();
            if (tid == 0) bumpcnt(isR ? &g_rhcnt[gchunk] : &g_ucnt[gchunk]);
        }

        // ================= cand phase =================
        {
            float2 cxv[2], hvp2[2];
            #pragma unroll
            for (int half = 0; half < 2; half++) {
                int row = r0 + half * 8;
                int col = ccol0 + ecol;
                cxv[half]  = __ldcg((const float2*)(XCt + (size_t)row * HD + col));
                hvp2[half] = __ldcg((const float2*)(hIn + (size_t)row * 1024 + col));
            }

            float acc[4] = {0.f, 0.f, 0.f, 0.f};
            #pragma unroll
            for (int p = 0; p < 3; p++) {
                waitcnt(&g_rhcnt[p], rT);
                const __nv_bfloat16* src = rhOut + (size_t)srow * 1024 + p * 128 + scb * 8;
                uint32_t dst = stB + (uint32_t)p * 34816u + sdst_off;
                #pragma unroll
                for (int c = 0; c < 8; c++) cp16(dst + c * 16, src + c * 8);
                CP_COMMIT();
            }
            for (int chunk = 0; chunk < 8; chunk++) {
                if (chunk < 5) {
                    waitcnt(&g_rhcnt[chunk + 3], rT);
                    const __nv_bfloat16* src = rhOut + (size_t)srow * 1024 + (chunk + 3) * 128 + scb * 8;
                    uint32_t dst = stB + (uint32_t)((chunk + 3) & 3) * 34816u + sdst_off;
                    #pragma unroll
                    for (int c = 0; c < 8; c++) cp16(dst + c * 16, src + c * 8);
                    CP_COMMIT();
                    CP_WAIT(3);
                } else {
                    CP_WAIT(0);
                }
                __syncthreads();
                uint32_t aB = stB + (uint32_t)(chunk & 3) * 34816u;
                #pragma unroll
                for (int ks = 0; ks < 8; ks++) {
                    int kloc = ks * 16;
                    int kg = chunk * 128 + kloc;
                    uint32_t af[4];
                    ldmatrix_x4(af[0], af[1], af[2], af[3],
                        aB + (uint32_t)((wid * 16 + arow_l) * 272 + (kloc + acol_l) * 2));
                    uint32_t bf2[2];
                    ldmatrix_x2(bf2[0], bf2[1],
                        wcB + (uint32_t)((l16 & 7) * 2064 + (kg + (l16 >> 3) * 8) * 2));
                    mma16816(acc, af, bf2);
                }
                __syncthreads();
            }

            // wait for the U chunk covering our cand columns, then finish
            waitcnt(&g_ucnt[cchunk], rT);
            #pragma unroll
            for (int half = 0; half < 2; half++) {
                int row = r0 + half * 8;
                int col = ccol0 + ecol;
                float2 uv = __ldcg((const float2*)(uOut + (size_t)row * 1024 + col));
                float ch0 = acc[half * 2 + 0];
                float ch1 = acc[half * 2 + 1];
                float cx0 = cxv[half].x, cx1 = cxv[half].y;
                float z0 = acv[0] * cx0 * ch0 + b1cv[0] * cx0 + b2cv[0] * ch0 + bcvv[0];
                float z1 = acv[1] * cx1 * ch1 + b1cv[1] * cx1 + b2cv[1] * ch1 + bcvv[1];
                float c0 = tanhf(z0), c1 = tanhf(z1);
                float hn0 = uv.x * hvp2[half].x + (1.f - uv.x) * c0;
                float hn1 = uv.y * hvp2[half].y + (1.f - uv.y) * c1;
                __stcg((float2*)(g_h + bo * (BD * HD) + (size_t)row * 1024 + col),
                       make_float2(hn0, hn1));
                __nv_bfloat162 p = __floats2bfloat162_rn(hn0, hn1);
                __stcg((uint32_t*)(g_hb + bo * (BD * HD) + (size_t)row * 1024 + col),
                       *(uint32_t*)&p);
                *(float2*)(outseq + (size_t)t * BD * HD + (size_t)row * HD + col) =
                    make_float2(hn0, hn1);
            }
            __syncthreads();
            if (tid == 0) bumpcnt(&g_hcnt[cchunk]);
        }
    }
}

// ---------------- NCE ----------------
__global__ __launch_bounds__(256)
void k_nce_samp(float* __restrict__ outsum)
{
    __shared__ float As[8][132];
    __shared__ float Bs[8][64];
    __shared__ float red[256];
    const int tid = threadIdx.x;
    const int rowBase = blockIdx.x * 128;

    const int arow = tid >> 1;
    const int acol = (tid & 1) << 2;
    int gi = rowBase + arow;
    size_t aoff = (size_t)((gi & 255) * BD + (gi >> 8)) * HD;

    const int brow = tid >> 5;
    const int bcl  = (tid & 31) << 1;
    const int ty = tid >> 4;
    const int tx = tid & 15;

    float acc[8][4];
    #pragma unroll
    for (int i = 0; i < 8; i++)
        #pragma unroll
        for (int j = 0; j < 4; j++) acc[i][j] = 0.f;

    for (int k0 = 0; k0 < HD; k0 += 8) {
        float4 av = *(const float4*)(g_O1 + aoff + k0 + acol);
        As[acol + 0][arow] = av.x;
        As[acol + 1][arow] = av.y;
        As[acol + 2][arow] = av.z;
        As[acol + 3][arow] = av.w;
        float2 bw = *(const float2*)(g_sampWT + (size_t)(k0 + brow) * SD + bcl);
        Bs[brow][bcl]     = bw.x;
        Bs[brow][bcl + 1] = bw.y;
        __syncthreads();
        #pragma unroll
        for (int k = 0; k < 8; k++) {
            float ar[8], br[4];
            *(float4*)&ar[0] = *(const float4*)&As[k][ty * 8];
            *(float4*)&ar[4] = *(const float4*)&As[k][ty * 8 + 4];
            *(float4*)&br[0] = *(const float4*)&Bs[k][tx * 4];
            #pragma unroll
            for (int i = 0; i < 8; i++)
                #pragma unroll
                for (int j = 0; j < 4; j++)
                    acc[i][j] += ar[i] * br[j];
        }
        __syncthreads();
    }

    float s = 0.f;
    #pragma unroll
    for (int j = 0; j < 4; j++) {
        float sbv = g_sampB[tx * 4 + j];
        #pragma unroll
        for (int i = 0; i < 8; i++)
            s += softplusf(acc[i][j] + sbv);
    }
    red[tid] = s;
    __syncthreads();
    for (int o = 128; o > 0; o >>= 1) {
        if (tid < o) red[tid] += red[tid + o];
        __syncthreads();
    }
    if (tid == 0) atomicAdd(outsum, red[0] * (1.f / 32768.f));
}

__global__ __launch_bounds__(256)
void k_nce_true(const int* __restrict__ targets, const float* __restrict__ sw,
                const float* __restrict__ sb, float* __restrict__ outsum)
{
    __shared__ float red[8];
    const int warp = threadIdx.x >> 5;
    const int lane = threadIdx.x & 31;
    const int i = blockIdx.x * 8 + warp;
    const int label = targets[i];
    const float* orow = g_O1 + (size_t)((i & 255) * BD + (i >> 8)) * HD;
    const float* wrow = sw + (size_t)label * HD;

    float s = 0.f;
    #pragma unroll
    for (int k0 = 0; k0 < HD; k0 += 128) {
        float4 a = *(const float4*)(orow + k0 + lane * 4);
        float4 w = *(const float4*)(wrow + k0 + lane * 4);
        s += a.x * w.x + a.y * w.y + a.z * w.z + a.w * w.w;
    }
    #pragma unroll
    for (int o = 16; o > 0; o >>= 1) s += __shfl_xor_sync(0xffffffffu, s, o);
    if (lane == 0) {
        float logit = s + sb[label];
        red[warp] = softplusf(-logit);
    }
    __syncthreads();
    if (threadIdx.x == 0) {
        float t = 0.f;
        #pragma unroll
        for (int w = 0; w < 8; w++) t += red[w];
        atomicAdd(outsum, t * (1.f / 32768.f));
    }
}

// ---------------- launch ----------------
extern "C" void kernel_launch(void* const* d_in, const int* in_sizes, int n_in,
                              void* d_out, int out_size)
{
    const int*   input_data = (const int*)  d_in[0];
    const int*   targets    = (const int*)  d_in[1];
    const int*   nce        = (const int*)  d_in[2];
    const float* embedding  = (const float*)d_in[3];
    const float* win        = (const float*)d_in[4];
    const float* bin_       = (const float*)d_in[5];
    const float* Wxg        = (const float*)d_in[6];
    const float* Whg        = (const float*)d_in[7];
    const float* ag         = (const float*)d_in[8];
    const float* b1g        = (const float*)d_in[9];
    const float* b2g        = (const float*)d_in[10];
    const float* bg         = (const float*)d_in[11];
    const float* Wxc        = (const float*)d_in[12];
    const float* Whc        = (const float*)d_in[13];
    const float* ac         = (const float*)d_in[14];
    const float* b1c        = (const float*)d_in[15];
    const float* b2c        = (const float*)d_in[16];
    const float* bc         = (const float*)d_in[17];
    const float* softmax_w  = (const float*)d_in[18];
    const float* softmax_b  = (const float*)d_in[19];
    float* out = (float*)d_out;

    float *pX, *pXG, *pXC, *pO0, *pO1;
    int* pidx;
    __nv_bfloat16 *pAb, *pEb, *pWbT;
    cudaGetSymbolAddress((void**)&pX,  g_X);
    cudaGetSymbolAddress((void**)&pXG, g_XG);
    cudaGetSymbolAddress((void**)&pXC, g_XC);
    cudaGetSymbolAddress((void**)&pO0, g_O0);
    cudaGetSymbolAddress((void**)&pO1, g_O1);
    cudaGetSymbolAddress((void**)&pidx, g_rowidx);
    cudaGetSymbolAddress((void**)&pAb, g_Ab);
    cudaGetSymbolAddress((void**)&pEb, g_Eb);
    cudaGetSymbolAddress((void**)&pWbT, g_WbT);

    cudaFuncSetAttribute(k_layer5,
                         cudaFuncAttributeMaxDynamicSharedMemorySize, 188800);

    k_zero_out<<<1, 32>>>(out, out_size);
    k_zero_sync<<<1, 32>>>();
    k_rowidx<<<TB / 256, 256>>>(input_data);
    k_gather_samp<<<SD, 256>>>(nce, softmax_w, softmax_b);

    k_f2b<<<(VD * ED / 4) / 256, 256>>>(embedding, pEb, VD * ED / 4);
    k_f2bTt<<<dim3(HD / 32, ED / 32), dim3(32, 8)>>>(win, pWbT, HD, ED);

    k_mgemm<true, true><<<dim3(HD / 128, TB / 128), 256>>>(
        pEb, pWbT, bin_, pX, HD, pidx);

    const float* inpF = pX;
    float* outb[2] = {pO0, pO1};
    for (int l = 0; l < LD; l++) {
        k_f2b<<<((size_t)TB * HD / 4) / 256, 256>>>(inpF, pAb, TB * HD / 4);

        k_f2bTt<<<dim3(H2 / 32, HD / 32), dim3(32, 8)>>>(
            Wxg + (size_t)l * HD * H2, pWbT, H2, HD);
        k_mgemm<false, false><<<dim3(H2 / 128, TB / 128), 256>>>(
            pAb, pWbT, nullptr, pXG, H2, nullptr);

        k_f2bTt<<<dim3(HD / 32, HD / 32), dim3(32, 8)>>>(
            Wxc + (size_t)l * HD * HD, pWbT, HD, HD);
        k_mgemm<false, false><<<dim3(HD / 128, TB / 128), 256>>>(
            pAb, pWbT, nullptr, pXC, HD, nullptr);

        // persistent recurrence, counter-synchronized
        unsigned gsTarget = (unsigned)(l + 1) * 128u;
        unsigned hB = (unsigned)l * 16u * TD;
        unsigned rB = (unsigned)l * 8u * TD;
        k_layer5<<<128, 256, 188800>>>(
            Whg + (size_t)l * HD * H2, Whc + (size_t)l * HD * HD,
            pXG, pXC,
            ag  + (size_t)l * H2, b1g + (size_t)l * H2,
            b2g + (size_t)l * H2, bg  + (size_t)l * H2,
            ac  + (size_t)l * HD, b1c + (size_t)l * HD,
            b2c + (size_t)l * HD, bc  + (size_t)l * HD,
            outb[l], gsTarget, hB, rB);
        inpF = outb[l];
    }

    k_nce_true<<<TB / 8, 256>>>(targets, softmax_w, softmax_b, out);
    k_nce_samp<<<TB / 128, 256>>>(out);
}

// round 11
// speedup vs baseline: 1.0586x; 1.0399x over previous
#include <cuda_runtime.h>
#include <cuda_bf16.h>
#include <stdint.h>
#include <math.h>

// Problem constants
#define VD 16384
#define ED 1024
#define HD 1024
#define H2 2048
#define LD 2
#define BD 128
#define TD 256
#define SD 64
#define TB 32768   // B*T
#define NG 3072    // fused gate+cand projection width

// ---------------- scratch (__device__ globals; no allocations allowed) -------------
__device__ float g_X  [(size_t)TB * HD];
__device__ float g_XGC[(size_t)TB * NG];   // [T,B,3072]: cols 0..2047 gate, 2048.. cand
__device__ float g_O0 [(size_t)TB * HD];
__device__ float g_O1 [(size_t)TB * HD];
__device__ float g_h [BD * HD];
__device__ __nv_bfloat16 g_hb [BD * HD];
__device__ __nv_bfloat16 g_RHb[BD * HD];
__device__ float g_U [BD * HD];
__device__ float g_sampWT[HD * SD];
__device__ float g_sampB [SD];
__device__ int   g_rowidx[TB];
__device__ unsigned g_barc[8];             // distributed barrier cells

__device__ __nv_bfloat16 g_Ab [(size_t)TB * HD];
__device__ __nv_bfloat16 g_Eb [(size_t)VD * ED];
__device__ __nv_bfloat16 g_WbT[(size_t)NG * HD];   // fused transposed weights [3072,1024]

__device__ __forceinline__ float softplusf(float x) {
    return fmaxf(x, 0.f) + log1pf(expf(-fabsf(x)));
}

// ---------------- PTX helpers ----------------
__device__ __forceinline__ uint32_t s2u(const void* p) {
    uint32_t a;
    asm("{ .reg .u64 t; cvta.to.shared.u64 t, %1; cvt.u32.u64 %0, t; }" : "=r"(a) : "l"(p));
    return a;
}
__device__ __forceinline__ void cp16(uint32_t dst, const void* src) {
    asm volatile("cp.async.cg.shared.global [%0], [%1], 16;" :: "r"(dst), "l"(src));
}
#define CP_COMMIT() asm volatile("cp.async.commit_group;" ::: "memory")
#define CP_WAIT(n)  asm volatile("cp.async.wait_group %0;" :: "n"(n) : "memory")

__device__ __forceinline__ void ldmatrix_x4(uint32_t& r0, uint32_t& r1,
                                            uint32_t& r2, uint32_t& r3, uint32_t addr) {
    asm volatile("ldmatrix.sync.aligned.m8n8.x4.shared.b16 {%0,%1,%2,%3}, [%4];"
                 : "=r"(r0), "=r"(r1), "=r"(r2), "=r"(r3) : "r"(addr));
}
__device__ __forceinline__ void ldmatrix_x2(uint32_t& r0, uint32_t& r1, uint32_t addr) {
    asm volatile("ldmatrix.sync.aligned.m8n8.x2.shared.b16 {%0,%1}, [%2];"
                 : "=r"(r0), "=r"(r1) : "r"(addr));
}
__device__ __forceinline__ void mma16816(float* d, const uint32_t* a, const uint32_t* b) {
    asm volatile("mma.sync.aligned.m16n8k16.row.col.f32.bf16.bf16.f32 "
                 "{%0,%1,%2,%3},{%4,%5,%6,%7},{%8,%9},{%0,%1,%2,%3};"
                 : "+f"(d[0]), "+f"(d[1]), "+f"(d[2]), "+f"(d[3])
                 : "r"(a[0]), "r"(a[1]), "r"(a[2]), "r"(a[3]), "r"(b[0]), "r"(b[1]));
}

// distributed software grid barrier: arrivals spread over 8 cells
__device__ __forceinline__ void gsync(unsigned target) {
    __syncthreads();
    if (threadIdx.x == 0) {
        __threadfence();
        atomicAdd(&g_barc[blockIdx.x & 7], 1u);
        for (;;) {
            unsigned s = 0;
            #pragma unroll
            for (int i = 0; i < 8; i++) s += *(volatile unsigned*)&g_barc[i];
            if (s >= target) break;
            __nanosleep(16);
        }
        __threadfence();
    }
    __syncthreads();
}

// ---------------- setup: zero out + barrier cells + rowidx (one launch) -------------
__global__ void k_setup(const int* __restrict__ input_data, float* out, int out_size) {
    int r = blockIdx.x * blockDim.x + threadIdx.x;
    if (blockIdx.x == 0 && threadIdx.x < 8) g_barc[threadIdx.x] = 0u;
    if (blockIdx.x == 0 && threadIdx.x == 0)
        for (int i = 0; i < out_size; i++) out[i] = 0.f;
    if (r < TB) {
        int t = r >> 7, b = r & 127;
        g_rowidx[r] = input_data[b * TD + t];
    }
}

__global__ void k_gather_samp(const int* __restrict__ nce,
                              const float* __restrict__ sw,
                              const float* __restrict__ sb) {
    int s = blockIdx.x;
    int row = nce[s];
    const float* src = sw + (size_t)row * HD;
    for (int k = threadIdx.x; k < HD; k += blockDim.x)
        g_sampWT[k * SD + s] = src[k];
    if (threadIdx.x == 0) g_sampB[s] = sb[row];
}

// ---------------- fused conversions ----------------
// conv1: embedding -> bf16 (16384 blocks) + win transpose -> WbT rows 0..1023 (1024 tiles)
__global__ void k_conv1(const float* __restrict__ emb, const float* __restrict__ win) {
    const int bx = blockIdx.x;
    const int tid = threadIdx.x;
    if (bx < 16384) {
        int i = bx * 256 + tid;                       // float4 index
        float4 v = ((const float4*)emb)[i];
        __nv_bfloat162* o = (__nv_bfloat162*)g_Eb;
        o[2 * i + 0] = __floats2bfloat162_rn(v.x, v.y);
        o[2 * i + 1] = __floats2bfloat162_rn(v.z, v.w);
    } else {
        __shared__ float tile[32][33];
        int tidx = bx - 16384;                        // 0..1023
        int tn = tidx & 31, tk = tidx >> 5;           // 32 n-tiles, 32 k-tiles
        int n0 = tn * 32, k0 = tk * 32;
        int tx = tid & 31, ty = tid >> 5;             // 32 x 8
        #pragma unroll
        for (int j = 0; j < 4; j++)
            tile[ty + 8 * j][tx] = win[(size_t)(k0 + ty + 8 * j) * HD + n0 + tx];
        __syncthreads();
        #pragma unroll
        for (int j = 0; j < 4; j++)
            g_WbT[(size_t)(n0 + ty + 8 * j) * HD + k0 + tx] =
                __float2bfloat16(tile[tx][ty + 8 * j]);
    }
}

// conv2: A fp32 -> bf16 (32768 blocks) + fused Wxg/Wxc transpose -> WbT[3072,1024] (3072 tiles)
__global__ void k_conv2(const float* __restrict__ A,
                        const float* __restrict__ Wg,   // [1024,2048]
                        const float* __restrict__ Wc) { // [1024,1024]
    const int bx = blockIdx.x;
    const int tid = threadIdx.x;
    if (bx < 32768) {
        int i = bx * 256 + tid;
        float4 v = ((const float4*)A)[i];
        __nv_bfloat162* o = (__nv_bfloat162*)g_Ab;
        o[2 * i + 0] = __floats2bfloat162_rn(v.x, v.y);
        o[2 * i + 1] = __floats2bfloat162_rn(v.z, v.w);
    } else {
        __shared__ float tile[32][33];
        int tidx = bx - 32768;                        // 0..3071
        int tn = tidx % 96, tk = tidx / 96;           // 96 n-tiles, 32 k-tiles
        int n0 = tn * 32, k0 = tk * 32;
        int tx = tid & 31, ty = tid >> 5;
        #pragma unroll
        for (int j = 0; j < 4; j++) {
            int k = k0 + ty + 8 * j;
            int n = n0 + tx;
            tile[ty + 8 * j][tx] = (n < 2048) ? Wg[(size_t)k * H2 + n]
                                              : Wc[(size_t)k * HD + (n - 2048)];
        }
        __syncthreads();
        #pragma unroll
        for (int j = 0; j < 4; j++)
            g_WbT[(size_t)(n0 + ty + 8 * j) * HD + k0 + tx] =
                __float2bfloat16(tile[tx][ty + 8 * j]);
    }
}

// ---------------- bf16 mma.sync GEMM ----------------
#define LDP 40

template<bool GATHER, bool BIAS>
__global__ __launch_bounds__(256)
void k_mgemm(const __nv_bfloat16* __restrict__ A, const __nv_bfloat16* __restrict__ BT,
             const float* __restrict__ bias, float* __restrict__ C,
             int N, const int* __restrict__ gidx)
{
    __shared__ __align__(16) __nv_bfloat16 sA[2][128 * LDP];
    __shared__ __align__(16) __nv_bfloat16 sB[2][128 * LDP];

    const int tid = threadIdx.x;
    const int rowBase = blockIdx.y * 128;
    const int colBase = blockIdx.x * 128;

    const int lrow = tid & 127;
    const bool isB = tid >= 128;
    const __nv_bfloat16* src;
    if (isB) {
        src = BT + (size_t)(colBase + lrow) * 1024;
    } else {
        size_t ar = GATHER ? (size_t)gidx[rowBase + lrow] : (size_t)(rowBase + lrow);
        src = A + ar * 1024;
    }
    uint32_t dst0 = s2u(isB ? (const void*)&sB[0][lrow * LDP] : (const void*)&sA[0][lrow * LDP]);
    uint32_t dst1 = s2u(isB ? (const void*)&sB[1][lrow * LDP] : (const void*)&sA[1][lrow * LDP]);

    const int wid = tid >> 5, lane = tid & 31;
    const int mb = (wid & 1) * 64;
    const int nb = (wid >> 1) * 32;
    const int arow_l = (lane & 7) + ((lane >> 3) & 1) * 8;
    const int acol_l = (lane >> 4) * 8;
    const int brow_l = (lane & 7) + (lane >> 4) * 8;
    const int bcol_l = ((lane >> 3) & 1) * 8;
    const uint32_t aS0 = s2u(sA[0]), aS1 = s2u(sA[1]);
    const uint32_t bS0 = s2u(sB[0]), bS1 = s2u(sB[1]);

    float acc[4][4][4];
    #pragma unroll
    for (int mt = 0; mt < 4; mt++)
        #pragma unroll
        for (int nt = 0; nt < 4; nt++)
            #pragma unroll
            for (int q = 0; q < 4; q++) acc[mt][nt][q] = 0.f;

    const int S = 32;
    {
        const __nv_bfloat16* p = src;
        #pragma unroll
        for (int c = 0; c < 4; c++) cp16(dst0 + c * 16, p + c * 8);
        CP_COMMIT();
    }

    for (int s = 0; s < S; s++) {
        if (s + 1 < S) {
            uint32_t d = ((s + 1) & 1) ? dst1 : dst0;
            const __nv_bfloat16* p = src + (s + 1) * 32;
            #pragma unroll
            for (int c = 0; c < 4; c++) cp16(d + c * 16, p + c * 8);
            CP_COMMIT();
            CP_WAIT(1);
        } else {
            CP_WAIT(0);
        }
        __syncthreads();

        const uint32_t aS = (s & 1) ? aS1 : aS0;
        const uint32_t bS = (s & 1) ? bS1 : bS0;
        #pragma unroll
        for (int kk = 0; kk < 32; kk += 16) {
            uint32_t af[4][4];
            #pragma unroll
            for (int mt = 0; mt < 4; mt++) {
                uint32_t ad = aS + (uint32_t)(((mb + mt * 16 + arow_l) * LDP) + kk + acol_l) * 2u;
                ldmatrix_x4(af[mt][0], af[mt][1], af[mt][2], af[mt][3], ad);
            }
            uint32_t bf[2][4];
            #pragma unroll
            for (int nt2 = 0; nt2 < 2; nt2++) {
                uint32_t bd = bS + (uint32_t)(((nb + nt2 * 16 + brow_l) * LDP) + kk + bcol_l) * 2u;
                ldmatrix_x4(bf[nt2][0], bf[nt2][1], bf[nt2][2], bf[nt2][3], bd);
            }
            #pragma unroll
            for (int mt = 0; mt < 4; mt++)
                #pragma unroll
                for (int nt = 0; nt < 4; nt++)
                    mma16816(acc[mt][nt], af[mt], &bf[nt >> 1][(nt & 1) * 2]);
        }
        __syncthreads();
    }

    const int erow = lane >> 2;
    const int ecol = (lane & 3) * 2;
    #pragma unroll
    for (int mt = 0; mt < 4; mt++) {
        #pragma unroll
        for (int nt = 0; nt < 4; nt++) {
            int r0 = rowBase + mb + mt * 16 + erow;
            int c0 = colBase + nb + nt * 8 + ecol;
            float b0 = 0.f, b1 = 0.f;
            if (BIAS) { b0 = bias[c0]; b1 = bias[c0 + 1]; }
            float2 v0 = make_float2(acc[mt][nt][0] + b0, acc[mt][nt][1] + b1);
            float2 v1 = make_float2(acc[mt][nt][2] + b0, acc[mt][nt][3] + b1);
            *(float2*)&C[(size_t)r0 * N + c0] = v0;
            *(float2*)&C[(size_t)(r0 + 8) * N + c0] = v1;
        }
    }
}

// ---------------- persistent per-layer MI-GRU recurrence (round-8 structure) --------
// 128 CTAs x 256 threads. CTA owns gate cols [cta*16,+16) and cand cols [cta*8,+8).
// 4-stage cp.async pipeline, epilogue prefetch, weights in SMEM bf16, 2 barriers/step.
__global__ __launch_bounds__(256)
void k_layerX(const float* __restrict__ Whg, const float* __restrict__ Whc,
              const float* __restrict__ XGC,
              const float* __restrict__ ag, const float* __restrict__ b1g,
              const float* __restrict__ b2g, const float* __restrict__ bg,
              const float* __restrict__ ac, const float* __restrict__ b1c,
              const float* __restrict__ b2c, const float* __restrict__ bcv,
              float* __restrict__ outseq, unsigned barBase)
{
    extern __shared__ char smRaw[];
    __nv_bfloat16* Wg  = (__nv_bfloat16*)smRaw;       // [16][1032] bf16 = 33024B
    __nv_bfloat16* Wc  = Wg + 16 * 1032;              // [8][1032]  = 16512B
    __nv_bfloat16* stg = Wc + 8 * 1032;               // 4 stages x 128x136 = 139264B

    const int cta = blockIdx.x;
    const unsigned nCTA = gridDim.x;
    const int tid = threadIdx.x;
    const int wid = tid >> 5, lane = tid & 31;
    const int gcol0 = cta * 16, ccol0 = cta * 8;
    const bool isR = (cta < 64);

    for (int i = tid; i < 16 * 1024; i += 256) {
        int n = i & 15, k = i >> 4;
        Wg[n * 1032 + k] = __float2bfloat16(Whg[(size_t)k * H2 + gcol0 + n]);
    }
    for (int i = tid; i < 8 * 1024; i += 256) {
        int n = i & 7, k = i >> 3;
        Wc[n * 1032 + k] = __float2bfloat16(Whc[(size_t)k * HD + ccol0 + n]);
    }

    const int arow_l = (lane & 7) + ((lane >> 3) & 1) * 8;
    const int acol_l = (lane >> 4) * 8;
    const int brow_l = (lane & 7) + (lane >> 4) * 8;
    const int bcol_l = ((lane >> 3) & 1) * 8;
    const int l16 = lane & 15;

    const uint32_t stB = s2u(stg);
    const uint32_t wgB = s2u(Wg);
    const uint32_t wcB = s2u(Wc);

    const int erow = lane >> 2;
    const int ecol = (lane & 3) * 2;
    const int r0 = wid * 16 + erow;

    float agv[2][2], b1v[2][2], b2v[2][2], bgv[2][2];
    #pragma unroll
    for (int nt = 0; nt < 2; nt++)
        #pragma unroll
        for (int j = 0; j < 2; j++) {
            int col = gcol0 + nt * 8 + ecol + j;
            agv[nt][j] = ag[col]; b1v[nt][j] = b1g[col];
            b2v[nt][j] = b2g[col]; bgv[nt][j] = bg[col];
        }
    float acv[2], b1cv[2], b2cv[2], bcvv[2];
    #pragma unroll
    for (int j = 0; j < 2; j++) {
        int col = ccol0 + ecol + j;
        acv[j] = ac[col]; b1cv[j] = b1c[col];
        b2cv[j] = b2c[col]; bcvv[j] = bcv[col];
    }

    const int srow = tid & 127;
    const int scb  = (tid >> 7) * 8;
    const uint32_t sdst_off = (uint32_t)(srow * 272 + scb * 16);

    {
        float4 z = make_float4(0.f, 0.f, 0.f, 0.f);
        __stcg((float4*)(g_h + cta * 1024 + tid * 4), z);
        uint2 zb = make_uint2(0u, 0u);
        __stcg((uint2*)(g_hb + cta * 1024 + tid * 4), zb);
    }
    unsigned bar = barBase + 1;
    gsync(bar * nCTA);

    for (int t = 0; t < TD; t++) {
        const float* Xt = XGC + (size_t)t * BD * NG;

        // ================= gate phase =================
        {
            float2 gxv[2][2], hvp[2][2];
            #pragma unroll
            for (int nt = 0; nt < 2; nt++)
                #pragma unroll
                for (int half = 0; half < 2; half++) {
                    int row = r0 + half * 8;
                    int col = gcol0 + nt * 8 + ecol;
                    gxv[nt][half] = __ldcg((const float2*)(Xt + (size_t)row * NG + col));
                    if (isR)
                        hvp[nt][half] = __ldcg((const float2*)(g_h + (size_t)row * 1024 + col));
                }

            float acc[2][4];
            #pragma unroll
            for (int nt = 0; nt < 2; nt++)
                #pragma unroll
                for (int q = 0; q < 4; q++) acc[nt][q] = 0.f;

            #pragma unroll
            for (int p = 0; p < 3; p++) {
                const __nv_bfloat16* src = g_hb + (size_t)srow * 1024 + p * 128 + scb * 8;
                uint32_t dst = stB + (uint32_t)p * 34816u + sdst_off;
                #pragma unroll
                for (int c = 0; c < 8; c++) cp16(dst + c * 16, src + c * 8);
                CP_COMMIT();
            }
            for (int chunk = 0; chunk < 8; chunk++) {
                if (chunk < 5) {
                    const __nv_bfloat16* src = g_hb + (size_t)srow * 1024 + (chunk + 3) * 128 + scb * 8;
                    uint32_t dst = stB + (uint32_t)((chunk + 3) & 3) * 34816u + sdst_off;
                    #pragma unroll
                    for (int c = 0; c < 8; c++) cp16(dst + c * 16, src + c * 8);
                    CP_COMMIT();
                    CP_WAIT(3);
                } else {
                    CP_WAIT(0);
                }
                __syncthreads();
                uint32_t aB = stB + (uint32_t)(chunk & 3) * 34816u;
                #pragma unroll
                for (int ks = 0; ks < 8; ks++) {
                    int kloc = ks * 16;
                    int kg = chunk * 128 + kloc;
                    uint32_t af[4];
                    ldmatrix_x4(af[0], af[1], af[2], af[3],
                        aB + (uint32_t)((wid * 16 + arow_l) * 272 + (kloc + acol_l) * 2));
                    uint32_t bf[4];
                    ldmatrix_x4(bf[0], bf[1], bf[2], bf[3],
                        wgB + (uint32_t)(brow_l * 2064 + (kg + bcol_l) * 2));
                    mma16816(acc[0], af, &bf[0]);
                    mma16816(acc[1], af, &bf[2]);
                }
                __syncthreads();
            }

            #pragma unroll
            for (int nt = 0; nt < 2; nt++) {
                #pragma unroll
                for (int half = 0; half < 2; half++) {
                    int row = r0 + half * 8;
                    int col = gcol0 + nt * 8 + ecol;
                    float gh0 = acc[nt][half * 2 + 0];
                    float gh1 = acc[nt][half * 2 + 1];
                    float gx0 = gxv[nt][half].x, gx1 = gxv[nt][half].y;
                    float z0 = agv[nt][0] * gx0 * gh0 + b1v[nt][0] * gx0 + b2v[nt][0] * gh0 + bgv[nt][0];
                    float z1 = agv[nt][1] * gx1 * gh1 + b1v[nt][1] * gx1 + b2v[nt][1] * gh1 + bgv[nt][1];
                    float s0 = 1.f / (1.f + expf(-z0));
                    float s1 = 1.f / (1.f + expf(-z1));
                    if (isR) {
                        __nv_bfloat162 p = __floats2bfloat162_rn(s0 * hvp[nt][half].x,
                                                                 s1 * hvp[nt][half].y);
                        __stcg((uint32_t*)(g_RHb + (size_t)row * 1024 + col), *(uint32_t*)&p);
                    } else {
                        __stcg((float2*)(g_U + (size_t)row * 1024 + (col - 1024)),
                               make_float2(s0, s1));
                    }
                }
            }
        }
        bar++; gsync(bar * nCTA);

        // ================= cand phase =================
        {
            float2 cxv[2], uvp[2], hvp2[2];
            #pragma unroll
            for (int half = 0; half < 2; half++) {
                int row = r0 + half * 8;
                int col = ccol0 + ecol;
                cxv[half]  = __ldcg((const float2*)(Xt + (size_t)row * NG + 2048 + col));
                uvp[half]  = __ldcg((const float2*)(g_U + (size_t)row * 1024 + col));
                hvp2[half] = __ldcg((const float2*)(g_h + (size_t)row * 1024 + col));
            }

            float acc[4] = {0.f, 0.f, 0.f, 0.f};
            #pragma unroll
            for (int p = 0; p < 3; p++) {
                const __nv_bfloat16* src = g_RHb + (size_t)srow * 1024 + p * 128 + scb * 8;
                uint32_t dst = stB + (uint32_t)p * 34816u + sdst_off;
                #pragma unroll
                for (int c = 0; c < 8; c++) cp16(dst + c * 16, src + c * 8);
                CP_COMMIT();
            }
            for (int chunk = 0; chunk < 8; chunk++) {
                if (chunk < 5) {
                    const __nv_bfloat16* src = g_RHb + (size_t)srow * 1024 + (chunk + 3) * 128 + scb * 8;
                    uint32_t dst = stB + (uint32_t)((chunk + 3) & 3) * 34816u + sdst_off;
                    #pragma unroll
                    for (int c = 0; c < 8; c++) cp16(dst + c * 16, src + c * 8);
                    CP_COMMIT();
                    CP_WAIT(3);
                } else {
                    CP_WAIT(0);
                }
                __syncthreads();
                uint32_t aB = stB + (uint32_t)(chunk & 3) * 34816u;
                #pragma unroll
                for (int ks = 0; ks < 8; ks++) {
                    int kloc = ks * 16;
                    int kg = chunk * 128 + kloc;
                    uint32_t af[4];
                    ldmatrix_x4(af[0], af[1], af[2], af[3],
                        aB + (uint32_t)((wid * 16 + arow_l) * 272 + (kloc + acol_l) * 2));
                    uint32_t bf2[2];
                    ldmatrix_x2(bf2[0], bf2[1],
                        wcB + (uint32_t)((l16 & 7) * 2064 + (kg + (l16 >> 3) * 8) * 2));
                    mma16816(acc, af, bf2);
                }
                __syncthreads();
            }

            #pragma unroll
            for (int half = 0; half < 2; half++) {
                int row = r0 + half * 8;
                int col = ccol0 + ecol;
                float ch0 = acc[half * 2 + 0];
                float ch1 = acc[half * 2 + 1];
                float cx0 = cxv[half].x, cx1 = cxv[half].y;
                float z0 = acv[0] * cx0 * ch0 + b1cv[0] * cx0 + b2cv[0] * ch0 + bcvv[0];
                float z1 = acv[1] * cx1 * ch1 + b1cv[1] * cx1 + b2cv[1] * ch1 + bcvv[1];
                float c0 = tanhf(z0), c1 = tanhf(z1);
                float hn0 = uvp[half].x * hvp2[half].x + (1.f - uvp[half].x) * c0;
                float hn1 = uvp[half].y * hvp2[half].y + (1.f - uvp[half].y) * c1;
                __stcg((float2*)(g_h + (size_t)row * 1024 + col), make_float2(hn0, hn1));
                __nv_bfloat162 p = __floats2bfloat162_rn(hn0, hn1);
                __stcg((uint32_t*)(g_hb + (size_t)row * 1024 + col), *(uint32_t*)&p);
                *(float2*)(outseq + (size_t)t * BD * HD + (size_t)row * HD + col) =
                    make_float2(hn0, hn1);
            }
        }
        bar++; gsync(bar * nCTA);
    }
}

// ---------------- NCE ----------------
__global__ __launch_bounds__(256)
void k_nce_samp(float* __restrict__ outsum)
{
    __shared__ float As[8][132];
    __shared__ float Bs[8][64];
    __shared__ float red[256];
    const int tid = threadIdx.x;
    const int rowBase = blockIdx.x * 128;

    const int arow = tid >> 1;
    const int acol = (tid & 1) << 2;
    int gi = rowBase + arow;
    size_t aoff = (size_t)((gi & 255) * BD + (gi >> 8)) * HD;

    const int brow = tid >> 5;
    const int bcl  = (tid & 31) << 1;
    const int ty = tid >> 4;
    const int tx = tid & 15;

    float acc[8][4];
    #pragma unroll
    for (int i = 0; i < 8; i++)
        #pragma unroll
        for (int j = 0; j < 4; j++) acc[i][j] = 0.f;

    for (int k0 = 0; k0 < HD; k0 += 8) {
        float4 av = *(const float4*)(g_O1 + aoff + k0 + acol);
        As[acol + 0][arow] = av.x;
        As[acol + 1][arow] = av.y;
        As[acol + 2][arow] = av.z;
        As[acol + 3][arow] = av.w;
        float2 bw = *(const float2*)(g_sampWT + (size_t)(k0 + brow) * SD + bcl);
        Bs[brow][bcl]     = bw.x;
        Bs[brow][bcl + 1] = bw.y;
        __syncthreads();
        #pragma unroll
        for (int k = 0; k < 8; k++) {
            float ar[8], br[4];
            *(float4*)&ar[0] = *(const float4*)&As[k][ty * 8];
            *(float4*)&ar[4] = *(const float4*)&As[k][ty * 8 + 4];
            *(float4*)&br[0] = *(const float4*)&Bs[k][tx * 4];
            #pragma unroll
            for (int i = 0; i < 8; i++)
                #pragma unroll
                for (int j = 0; j < 4; j++)
                    acc[i][j] += ar[i] * br[j];
        }
        __syncthreads();
    }

    float s = 0.f;
    #pragma unroll
    for (int j = 0; j < 4; j++) {
        float sbv = g_sampB[tx * 4 + j];
        #pragma unroll
        for (int i = 0; i < 8; i++)
            s += softplusf(acc[i][j] + sbv);
    }
    red[tid] = s;
    __syncthreads();
    for (int o = 128; o > 0; o >>= 1) {
        if (tid < o) red[tid] += red[tid + o];
        __syncthreads();
    }
    if (tid == 0) atomicAdd(outsum, red[0] * (1.f / 32768.f));
}

__global__ __launch_bounds__(256)
void k_nce_true(const int* __restrict__ targets, const float* __restrict__ sw,
                const float* __restrict__ sb, float* __restrict__ outsum)
{
    __shared__ float red[8];
    const int warp = threadIdx.x >> 5;
    const int lane = threadIdx.x & 31;
    const int i = blockIdx.x * 8 + warp;
    const int label = targets[i];
    const float* orow = g_O1 + (size_t)((i & 255) * BD + (i >> 8)) * HD;
    const float* wrow = sw + (size_t)label * HD;

    float s = 0.f;
    #pragma unroll
    for (int k0 = 0; k0 < HD; k0 += 128) {
        float4 a = *(const float4*)(orow + k0 + lane * 4);
        float4 w = *(const float4*)(wrow + k0 + lane * 4);
        s += a.x * w.x + a.y * w.y + a.z * w.z + a.w * w.w;
    }
    #pragma unroll
    for (int o = 16; o > 0; o >>= 1) s += __shfl_xor_sync(0xffffffffu, s, o);
    if (lane == 0) {
        float logit = s + sb[label];
        red[warp] = softplusf(-logit);
    }
    __syncthreads();
    if (threadIdx.x == 0) {
        float t = 0.f;
        #pragma unroll
        for (int w = 0; w < 8; w++) t += red[w];
        atomicAdd(outsum, t * (1.f / 32768.f));
    }
}

// ---------------- launch ----------------
extern "C" void kernel_launch(void* const* d_in, const int* in_sizes, int n_in,
                              void* d_out, int out_size)
{
    const int*   input_data = (const int*)  d_in[0];
    const int*   targets    = (const int*)  d_in[1];
    const int*   nce        = (const int*)  d_in[2];
    const float* embedding  = (const float*)d_in[3];
    const float* win        = (const float*)d_in[4];
    const float* bin_       = (const float*)d_in[5];
    const float* Wxg        = (const float*)d_in[6];
    const float* Whg        = (const float*)d_in[7];
    const float* ag         = (const float*)d_in[8];
    const float* b1g        = (const float*)d_in[9];
    const float* b2g        = (const float*)d_in[10];
    const float* bg         = (const float*)d_in[11];
    const float* Wxc        = (const float*)d_in[12];
    const float* Whc        = (const float*)d_in[13];
    const float* ac         = (const float*)d_in[14];
    const float* b1c        = (const float*)d_in[15];
    const float* b2c        = (const float*)d_in[16];
    const float* bc         = (const float*)d_in[17];
    const float* softmax_w  = (const float*)d_in[18];
    const float* softmax_b  = (const float*)d_in[19];
    float* out = (float*)d_out;

    float *pX, *pXGC, *pO0, *pO1;
    int* pidx;
    __nv_bfloat16 *pAb, *pEb, *pWbT;
    cudaGetSymbolAddress((void**)&pX,   g_X);
    cudaGetSymbolAddress((void**)&pXGC, g_XGC);
    cudaGetSymbolAddress((void**)&pO0,  g_O0);
    cudaGetSymbolAddress((void**)&pO1,  g_O1);
    cudaGetSymbolAddress((void**)&pidx, g_rowidx);
    cudaGetSymbolAddress((void**)&pAb,  g_Ab);
    cudaGetSymbolAddress((void**)&pEb,  g_Eb);
    cudaGetSymbolAddress((void**)&pWbT, g_WbT);

    cudaFuncSetAttribute(k_layerX,
                         cudaFuncAttributeMaxDynamicSharedMemorySize, 188800);

    // launch 1: setup (out zero + barrier cells + rowidx)
    k_setup<<<TB / 256, 256>>>(input_data, out, out_size);
    // launch 2: embedding->bf16 + win transpose
    k_conv1<<<16384 + 1024, 256>>>(embedding, win);
    // launch 3: X = gather(Eb) @ win + bin_
    k_mgemm<true, true><<<dim3(HD / 128, TB / 128), 256>>>(
        pEb, pWbT, bin_, pX, HD, pidx);

    const float* inpF = pX;
    float* outb[2] = {pO0, pO1};
    for (int l = 0; l < LD; l++) {
        // launch 4/7: A->bf16 + fused weight transpose
        k_conv2<<<32768 + 3072, 256>>>(inpF,
                                       Wxg + (size_t)l * HD * H2,
                                       Wxc + (size_t)l * HD * HD);
        // launch 5/8: XGC = A @ [Wxg|Wxc]  (N = 3072)
        k_mgemm<false, false><<<dim3(NG / 128, TB / 128), 256>>>(
            pAb, pWbT, nullptr, pXGC, NG, nullptr);

        // launch 6/9: persistent recurrence (6th launch overall for l=0 -> ncu target)
        unsigned barBase = (unsigned)l * (1u + 2u * TD);
        k_layerX<<<128, 256, 188800>>>(
            Whg + (size_t)l * HD * H2, Whc + (size_t)l * HD * HD,
            pXGC,
            ag  + (size_t)l * H2, b1g + (size_t)l * H2,
            b2g + (size_t)l * H2, bg  + (size_t)l * H2,
            ac  + (size_t)l * HD, b1c + (size_t)l * HD,
            b2c + (size_t)l * HD, bc  + (size_t)l * HD,
            outb[l], barBase);
        inpF = outb[l];
    }

    k_gather_samp<<<SD, 256>>>(nce, softmax_w, softmax_b);
    k_nce_true<<<TB / 8, 256>>>(targets, softmax_w, softmax_b, out);
    k_nce_samp<<<TB / 128, 256>>>(out);
}

// round 12
// speedup vs baseline: 1.1298x; 1.0672x over previous
#include <cuda_runtime.h>
#include <cuda_bf16.h>
#include <stdint.h>
#include <math.h>

// Problem constants
#define VD 16384
#define ED 1024
#define HD 1024
#define H2 2048
#define LD 2
#define BD 128
#define TD 256
#define SD 64
#define TB 32768   // B*T
#define NG 3072    // fused gate+cand projection width

// ---------------- scratch (__device__ globals; no allocations allowed) -------------
__device__ float g_XGC[(size_t)TB * NG];   // [T,B,3072]: 0..2047 gate, 2048.. cand
__device__ float g_O1 [(size_t)TB * HD];   // layer-1 fp32 outputs (NCE input)
__device__ float g_O0f[(size_t)TB * HD];   // layer-0 fp32 outputs (unused, kept cheap)
__device__ __nv_bfloat16 g_O0b[(size_t)TB * HD];  // layer-0 bf16 outputs (layer-1 A operand)
__device__ float g_h [BD * HD];
__device__ __nv_bfloat16 g_hb [BD * HD];
__device__ __nv_bfloat16 g_RHb[BD * HD];
__device__ float g_sampWT[HD * SD];
__device__ float g_sampB [SD];
__device__ int   g_rowidx[TB];
__device__ unsigned g_barcnt;

__device__ __nv_bfloat16 g_Ab  [(size_t)TB * HD];  // X in bf16 (layer-0 A operand)
__device__ __nv_bfloat16 g_Eb  [(size_t)VD * ED];
__device__ __nv_bfloat16 g_WbTw[(size_t)HD * HD];  // win^T bf16
__device__ __nv_bfloat16 g_WbT0[(size_t)NG * HD];  // [Wxg0|Wxc0]^T bf16
__device__ __nv_bfloat16 g_WbT1[(size_t)NG * HD];  // [Wxg1|Wxc1]^T bf16

__device__ __forceinline__ float softplusf(float x) {
    return fmaxf(x, 0.f) + log1pf(expf(-fabsf(x)));
}

// ---------------- PTX helpers ----------------
__device__ __forceinline__ uint32_t s2u(const void* p) {
    uint32_t a;
    asm("{ .reg .u64 t; cvta.to.shared.u64 t, %1; cvt.u32.u64 %0, t; }" : "=r"(a) : "l"(p));
    return a;
}
__device__ __forceinline__ void cp16(uint32_t dst, const void* src) {
    asm volatile("cp.async.cg.shared.global [%0], [%1], 16;" :: "r"(dst), "l"(src));
}
#define CP_COMMIT() asm volatile("cp.async.commit_group;" ::: "memory")
#define CP_WAIT(n)  asm volatile("cp.async.wait_group %0;" :: "n"(n) : "memory")

__device__ __forceinline__ void ldmatrix_x4(uint32_t& r0, uint32_t& r1,
                                            uint32_t& r2, uint32_t& r3, uint32_t addr) {
    asm volatile("ldmatrix.sync.aligned.m8n8.x4.shared.b16 {%0,%1,%2,%3}, [%4];"
                 : "=r"(r0), "=r"(r1), "=r"(r2), "=r"(r3) : "r"(addr));
}
__device__ __forceinline__ void ldmatrix_x2(uint32_t& r0, uint32_t& r1, uint32_t addr) {
    asm volatile("ldmatrix.sync.aligned.m8n8.x2.shared.b16 {%0,%1}, [%2];"
                 : "=r"(r0), "=r"(r1) : "r"(addr));
}
__device__ __forceinline__ void mma16816(float* d, const uint32_t* a, const uint32_t* b) {
    asm volatile("mma.sync.aligned.m16n8k16.row.col.f32.bf16.bf16.f32 "
                 "{%0,%1,%2,%3},{%4,%5,%6,%7},{%8,%9},{%0,%1,%2,%3};"
                 : "+f"(d[0]), "+f"(d[1]), "+f"(d[2]), "+f"(d[3])
                 : "r"(a[0]), "r"(a[1]), "r"(a[2]), "r"(a[3]), "r"(b[0]), "r"(b[1]));
}

// single-counter software grid barrier (round-8 proven form)
__device__ __forceinline__ void gsync(unsigned target) {
    __syncthreads();
    if (threadIdx.x == 0) {
        __threadfence();
        atomicAdd(&g_barcnt, 1u);
        while (*(volatile unsigned*)&g_barcnt < target) __nanosleep(16);
        __threadfence();
    }
    __syncthreads();
}

// ---------------- upfront fused kernel: setup + emb->bf16 + ALL weight transposes ---
// blocks [0,128): rowidx (+ block0: zero out/barcnt)
// blocks [128, 128+16384): embedding -> bf16
// blocks next 1024: win^T -> WbTw
// blocks next 3072: [Wxg0|Wxc0]^T -> WbT0
// blocks next 3072: [Wxg1|Wxc1]^T -> WbT1
__global__ void k_convW(const int* __restrict__ input_data, float* out, int out_size,
                        const float* __restrict__ emb, const float* __restrict__ win,
                        const float* __restrict__ Wxg, const float* __restrict__ Wxc)
{
    const int bx = blockIdx.x;
    const int tid = threadIdx.x;
    if (bx < 128) {
        if (bx == 0 && tid == 0) {
            g_barcnt = 0u;
            for (int i = 0; i < out_size; i++) out[i] = 0.f;
        }
        int r = bx * 256 + tid;
        int t = r >> 7, b = r & 127;
        g_rowidx[r] = input_data[b * TD + t];
    } else if (bx < 128 + 16384) {
        int i = (bx - 128) * 256 + tid;
        float4 v = ((const float4*)emb)[i];
        __nv_bfloat162* o = (__nv_bfloat162*)g_Eb;
        o[2 * i + 0] = __floats2bfloat162_rn(v.x, v.y);
        o[2 * i + 1] = __floats2bfloat162_rn(v.z, v.w);
    } else {
        __shared__ float tile[32][33];
        const int tx = tid & 31, ty = tid >> 5;   // 32 x 8
        if (bx < 128 + 16384 + 1024) {
            int idx = bx - (128 + 16384);
            int n0 = (idx & 31) * 32, k0 = (idx >> 5) * 32;
            #pragma unroll
            for (int j = 0; j < 4; j++)
                tile[ty + 8 * j][tx] = win[(size_t)(k0 + ty + 8 * j) * HD + n0 + tx];
            __syncthreads();
            #pragma unroll
            for (int j = 0; j < 4; j++)
                g_WbTw[(size_t)(n0 + ty + 8 * j) * HD + k0 + tx] =
                    __float2bfloat16(tile[tx][ty + 8 * j]);
        } else {
            int idx = bx - (128 + 16384 + 1024);
            int l = idx / 3072;
            idx -= l * 3072;
            const float* Wg = Wxg + (size_t)l * HD * H2;
            const float* Wc = Wxc + (size_t)l * HD * HD;
            __nv_bfloat16* dst = l ? g_WbT1 : g_WbT0;
            int n0 = (idx % 96) * 32, k0 = (idx / 96) * 32;
            #pragma unroll
            for (int j = 0; j < 4; j++) {
                int k = k0 + ty + 8 * j;
                int n = n0 + tx;
                tile[ty + 8 * j][tx] = (n < 2048) ? Wg[(size_t)k * H2 + n]
                                                  : Wc[(size_t)k * HD + (n - 2048)];
            }
            __syncthreads();
            #pragma unroll
            for (int j = 0; j < 4; j++)
                dst[(size_t)(n0 + ty + 8 * j) * HD + k0 + tx] =
                    __float2bfloat16(tile[tx][ty + 8 * j]);
        }
    }
}

__global__ void k_gather_samp(const int* __restrict__ nce,
                              const float* __restrict__ sw,
                              const float* __restrict__ sb) {
    int s = blockIdx.x;
    int row = nce[s];
    const float* src = sw + (size_t)row * HD;
    for (int k = threadIdx.x; k < HD; k += blockDim.x)
        g_sampWT[k * SD + s] = src[k];
    if (threadIdx.x == 0) g_sampB[s] = sb[row];
}

// ---------------- bf16 mma.sync GEMM (fp32 or bf16 output) ----------------
#define LDP 40

template<bool GATHER, bool BIAS, bool OB16>
__global__ __launch_bounds__(256)
void k_mgemm(const __nv_bfloat16* __restrict__ A, const __nv_bfloat16* __restrict__ BT,
             const float* __restrict__ bias, float* __restrict__ Cf,
             __nv_bfloat16* __restrict__ Cb, int N, const int* __restrict__ gidx)
{
    __shared__ __align__(16) __nv_bfloat16 sA[2][128 * LDP];
    __shared__ __align__(16) __nv_bfloat16 sB[2][128 * LDP];

    const int tid = threadIdx.x;
    const int rowBase = blockIdx.y * 128;
    const int colBase = blockIdx.x * 128;

    const int lrow = tid & 127;
    const bool isB = tid >= 128;
    const __nv_bfloat16* src;
    if (isB) {
        src = BT + (size_t)(colBase + lrow) * 1024;
    } else {
        size_t ar = GATHER ? (size_t)gidx[rowBase + lrow] : (size_t)(rowBase + lrow);
        src = A + ar * 1024;
    }
    uint32_t dst0 = s2u(isB ? (const void*)&sB[0][lrow * LDP] : (const void*)&sA[0][lrow * LDP]);
    uint32_t dst1 = s2u(isB ? (const void*)&sB[1][lrow * LDP] : (const void*)&sA[1][lrow * LDP]);

    const int wid = tid >> 5, lane = tid & 31;
    const int mb = (wid & 1) * 64;
    const int nb = (wid >> 1) * 32;
    const int arow_l = (lane & 7) + ((lane >> 3) & 1) * 8;
    const int acol_l = (lane >> 4) * 8;
    const int brow_l = (lane & 7) + (lane >> 4) * 8;
    const int bcol_l = ((lane >> 3) & 1) * 8;
    const uint32_t aS0 = s2u(sA[0]), aS1 = s2u(sA[1]);
    const uint32_t bS0 = s2u(sB[0]), bS1 = s2u(sB[1]);

    float acc[4][4][4];
    #pragma unroll
    for (int mt = 0; mt < 4; mt++)
        #pragma unroll
        for (int nt = 0; nt < 4; nt++)
            #pragma unroll
            for (int q = 0; q < 4; q++) acc[mt][nt][q] = 0.f;

    const int S = 32;
    {
        const __nv_bfloat16* p = src;
        #pragma unroll
        for (int c = 0; c < 4; c++) cp16(dst0 + c * 16, p + c * 8);
        CP_COMMIT();
    }

    for (int s = 0; s < S; s++) {
        if (s + 1 < S) {
            uint32_t d = ((s + 1) & 1) ? dst1 : dst0;
            const __nv_bfloat16* p = src + (s + 1) * 32;
            #pragma unroll
            for (int c = 0; c < 4; c++) cp16(d + c * 16, p + c * 8);
            CP_COMMIT();
            CP_WAIT(1);
        } else {
            CP_WAIT(0);
        }
        __syncthreads();

        const uint32_t aS = (s & 1) ? aS1 : aS0;
        const uint32_t bS = (s & 1) ? bS1 : bS0;
        #pragma unroll
        for (int kk = 0; kk < 32; kk += 16) {
            uint32_t af[4][4];
            #pragma unroll
            for (int mt = 0; mt < 4; mt++) {
                uint32_t ad = aS + (uint32_t)(((mb + mt * 16 + arow_l) * LDP) + kk + acol_l) * 2u;
                ldmatrix_x4(af[mt][0], af[mt][1], af[mt][2], af[mt][3], ad);
            }
            uint32_t bf[2][4];
            #pragma unroll
            for (int nt2 = 0; nt2 < 2; nt2++) {
                uint32_t bd = bS + (uint32_t)(((nb + nt2 * 16 + brow_l) * LDP) + kk + bcol_l) * 2u;
                ldmatrix_x4(bf[nt2][0], bf[nt2][1], bf[nt2][2], bf[nt2][3], bd);
            }
            #pragma unroll
            for (int mt = 0; mt < 4; mt++)
                #pragma unroll
                for (int nt = 0; nt < 4; nt++)
                    mma16816(acc[mt][nt], af[mt], &bf[nt >> 1][(nt & 1) * 2]);
        }
        __syncthreads();
    }

    const int erow = lane >> 2;
    const int ecol = (lane & 3) * 2;
    #pragma unroll
    for (int mt = 0; mt < 4; mt++) {
        #pragma unroll
        for (int nt = 0; nt < 4; nt++) {
            int r0 = rowBase + mb + mt * 16 + erow;
            int c0 = colBase + nb + nt * 8 + ecol;
            float b0 = 0.f, b1 = 0.f;
            if (BIAS) { b0 = bias[c0]; b1 = bias[c0 + 1]; }
            float v00 = acc[mt][nt][0] + b0, v01 = acc[mt][nt][1] + b1;
            float v10 = acc[mt][nt][2] + b0, v11 = acc[mt][nt][3] + b1;
            if (OB16) {
                __nv_bfloat162 p0 = __floats2bfloat162_rn(v00, v01);
                __nv_bfloat162 p1 = __floats2bfloat162_rn(v10, v11);
                *(__nv_bfloat162*)&Cb[(size_t)r0 * N + c0] = p0;
                *(__nv_bfloat162*)&Cb[(size_t)(r0 + 8) * N + c0] = p1;
            } else {
                *(float2*)&Cf[(size_t)r0 * N + c0] = make_float2(v00, v01);
                *(float2*)&Cf[(size_t)(r0 + 8) * N + c0] = make_float2(v10, v11);
            }
        }
    }
}

// ---------------- persistent per-layer MI-GRU recurrence ----------------------------
// 128 CTAs x 256 threads. CTA c owns r-gate cols [8c,8c+8), u-gate cols [1024+8c,+8),
// cand cols [8c,+8). u stays in registers across the phase barrier (no g_U).
// 4-stage cp.async pipeline, weights in SMEM bf16, 2 single-counter barriers/step.
__global__ __launch_bounds__(256)
void k_layerX(const float* __restrict__ Whg, const float* __restrict__ Whc,
              const float* __restrict__ XGC,
              const float* __restrict__ ag, const float* __restrict__ b1g,
              const float* __restrict__ b2g, const float* __restrict__ bg,
              const float* __restrict__ ac, const float* __restrict__ b1c,
              const float* __restrict__ b2c, const float* __restrict__ bcv,
              float* __restrict__ outF, __nv_bfloat16* __restrict__ outB,
              unsigned barBase)
{
    extern __shared__ char smRaw[];
    __nv_bfloat16* Wg  = (__nv_bfloat16*)smRaw;       // [16][1032] bf16 = 33024B
    __nv_bfloat16* Wc  = Wg + 16 * 1032;              // [8][1032]  = 16512B
    __nv_bfloat16* stg = Wc + 8 * 1032;               // 4 stages x 128x136 = 139264B

    const int cta = blockIdx.x;
    const unsigned nCTA = gridDim.x;
    const int tid = threadIdx.x;
    const int wid = tid >> 5, lane = tid & 31;
    const int col0 = cta * 8;                         // base for r / u / cand cols

    // weight slices -> SMEM: Wg rows 0-7 = r cols, rows 8-15 = u cols
    for (int i = tid; i < 16 * 1024; i += 256) {
        int n = i & 15, k = i >> 4;
        int col = (n < 8) ? (col0 + n) : (1024 + col0 + (n - 8));
        Wg[n * 1032 + k] = __float2bfloat16(Whg[(size_t)k * H2 + col]);
    }
    for (int i = tid; i < 8 * 1024; i += 256) {
        int n = i & 7, k = i >> 3;
        Wc[n * 1032 + k] = __float2bfloat16(Whc[(size_t)k * HD + col0 + n]);
    }

    const int arow_l = (lane & 7) + ((lane >> 3) & 1) * 8;
    const int acol_l = (lane >> 4) * 8;
    const int brow_l = (lane & 7) + (lane >> 4) * 8;
    const int bcol_l = ((lane >> 3) & 1) * 8;
    const int l16 = lane & 15;

    const uint32_t stB = s2u(stg);
    const uint32_t wgB = s2u(Wg);
    const uint32_t wcB = s2u(Wc);

    const int erow = lane >> 2;
    const int ecol = (lane & 3) * 2;
    const int r0 = wid * 16 + erow;

    // per-lane constants: r cols (col0+ecol+j), u cols (1024+col0+ecol+j), cand cols
    float agr[2], b1r[2], b2r[2], bgr[2];
    float agu[2], b1u[2], b2u[2], bgu[2];
    float acv[2], b1cv[2], b2cv[2], bcvv[2];
    #pragma unroll
    for (int j = 0; j < 2; j++) {
        int cr = col0 + ecol + j;
        int cu = 1024 + cr;
        agr[j] = ag[cr]; b1r[j] = b1g[cr]; b2r[j] = b2g[cr]; bgr[j] = bg[cr];
        agu[j] = ag[cu]; b1u[j] = b1g[cu]; b2u[j] = b2g[cu]; bgu[j] = bg[cu];
        acv[j] = ac[cr]; b1cv[j] = b1c[cr]; b2cv[j] = b2c[cr]; bcvv[j] = bcv[cr];
    }

    const int srow = tid & 127;
    const int scb  = (tid >> 7) * 8;
    const uint32_t sdst_off = (uint32_t)(srow * 272 + scb * 16);

    {
        float4 z = make_float4(0.f, 0.f, 0.f, 0.f);
        __stcg((float4*)(g_h + cta * 1024 + tid * 4), z);
        uint2 zb = make_uint2(0u, 0u);
        __stcg((uint2*)(g_hb + cta * 1024 + tid * 4), zb);
    }
    unsigned bar = barBase + 1;
    gsync(bar * nCTA);

    for (int t = 0; t < TD; t++) {
        const float* Xt = XGC + (size_t)t * BD * NG;
        float ur[2][2];          // update gate, kept in registers across the barrier
        float2 hvp[2];           // h at (row, col0+ecol), reused in both epilogues

        // ================= gate phase =================
        {
            float2 gxr[2], gxu[2];
            #pragma unroll
            for (int half = 0; half < 2; half++) {
                int row = r0 + half * 8;
                gxr[half] = __ldcg((const float2*)(Xt + (size_t)row * NG + col0 + ecol));
                gxu[half] = __ldcg((const float2*)(Xt + (size_t)row * NG + 1024 + col0 + ecol));
                hvp[half] = __ldcg((const float2*)(g_h + (size_t)row * 1024 + col0 + ecol));
            }

            float acc[2][4];
            #pragma unroll
            for (int nt = 0; nt < 2; nt++)
                #pragma unroll
                for (int q = 0; q < 4; q++) acc[nt][q] = 0.f;

            #pragma unroll
            for (int p = 0; p < 3; p++) {
                const __nv_bfloat16* src = g_hb + (size_t)srow * 1024 + p * 128 + scb * 8;
                uint32_t dst = stB + (uint32_t)p * 34816u + sdst_off;
                #pragma unroll
                for (int c = 0; c < 8; c++) cp16(dst + c * 16, src + c * 8);
                CP_COMMIT();
            }
            for (int chunk = 0; chunk < 8; chunk++) {
                if (chunk < 5) {
                    const __nv_bfloat16* src = g_hb + (size_t)srow * 1024 + (chunk + 3) * 128 + scb * 8;
                    uint32_t dst = stB + (uint32_t)((chunk + 3) & 3) * 34816u + sdst_off;
                    #pragma unroll
                    for (int c = 0; c < 8; c++) cp16(dst + c * 16, src + c * 8);
                    CP_COMMIT();
                    CP_WAIT(3);
                } else {
                    CP_WAIT(0);
                }
                __syncthreads();
                uint32_t aB = stB + (uint32_t)(chunk & 3) * 34816u;
                #pragma unroll
                for (int ks = 0; ks < 8; ks++) {
                    int kloc = ks * 16;
                    int kg = chunk * 128 + kloc;
                    uint32_t af[4];
                    ldmatrix_x4(af[0], af[1], af[2], af[3],
                        aB + (uint32_t)((wid * 16 + arow_l) * 272 + (kloc + acol_l) * 2));
                    uint32_t bf[4];
                    ldmatrix_x4(bf[0], bf[1], bf[2], bf[3],
                        wgB + (uint32_t)(brow_l * 2064 + (kg + bcol_l) * 2));
                    mma16816(acc[0], af, &bf[0]);
                    mma16816(acc[1], af, &bf[2]);
                }
                __syncthreads();
            }

            // epilogue: r -> RHb (bf16), u -> registers
            #pragma unroll
            for (int half = 0; half < 2; half++) {
                int row = r0 + half * 8;
                float gh0 = acc[0][half * 2 + 0], gh1 = acc[0][half * 2 + 1];
                float z0 = agr[0] * gxr[half].x * gh0 + b1r[0] * gxr[half].x + b2r[0] * gh0 + bgr[0];
                float z1 = agr[1] * gxr[half].y * gh1 + b1r[1] * gxr[half].y + b2r[1] * gh1 + bgr[1];
                float s0 = 1.f / (1.f + expf(-z0));
                float s1 = 1.f / (1.f + expf(-z1));
                __nv_bfloat162 p = __floats2bfloat162_rn(s0 * hvp[half].x, s1 * hvp[half].y);
                __stcg((uint32_t*)(g_RHb + (size_t)row * 1024 + col0 + ecol), *(uint32_t*)&p);

                float uh0 = acc[1][half * 2 + 0], uh1 = acc[1][half * 2 + 1];
                float y0 = agu[0] * gxu[half].x * uh0 + b1u[0] * gxu[half].x + b2u[0] * uh0 + bgu[0];
                float y1 = agu[1] * gxu[half].y * uh1 + b1u[1] * gxu[half].y + b2u[1] * uh1 + bgu[1];
                ur[half][0] = 1.f / (1.f + expf(-y0));
                ur[half][1] = 1.f / (1.f + expf(-y1));
            }
        }
        bar++; gsync(bar * nCTA);

        // ================= cand phase =================
        {
            float2 cxv[2];
            #pragma unroll
            for (int half = 0; half < 2; half++) {
                int row = r0 + half * 8;
                cxv[half] = __ldcg((const float2*)(Xt + (size_t)row * NG + 2048 + col0 + ecol));
            }

            float acc[4] = {0.f, 0.f, 0.f, 0.f};
            #pragma unroll
            for (int p = 0; p < 3; p++) {
                const __nv_bfloat16* src = g_RHb + (size_t)srow * 1024 + p * 128 + scb * 8;
                uint32_t dst = stB + (uint32_t)p * 34816u + sdst_off;
                #pragma unroll
                for (int c = 0; c < 8; c++) cp16(dst + c * 16, src + c * 8);
                CP_COMMIT();
            }
            for (int chunk = 0; chunk < 8; chunk++) {
                if (chunk < 5) {
                    const __nv_bfloat16* src = g_RHb + (size_t)srow * 1024 + (chunk + 3) * 128 + scb * 8;
                    uint32_t dst = stB + (uint32_t)((chunk + 3) & 3) * 34816u + sdst_off;
                    #pragma unroll
                    for (int c = 0; c < 8; c++) cp16(dst + c * 16, src + c * 8);
                    CP_COMMIT();
                    CP_WAIT(3);
                } else {
                    CP_WAIT(0);
                }
                __syncthreads();
                uint32_t aB = stB + (uint32_t)(chunk & 3) * 34816u;
                #pragma unroll
                for (int ks = 0; ks < 8; ks++) {
                    int kloc = ks * 16;
                    int kg = chunk * 128 + kloc;
                    uint32_t af[4];
                    ldmatrix_x4(af[0], af[1], af[2], af[3],
                        aB + (uint32_t)((wid * 16 + arow_l) * 272 + (kloc + acol_l) * 2));
                    uint32_t bf2[2];
                    ldmatrix_x2(bf2[0], bf2[1],
                        wcB + (uint32_t)((l16 & 7) * 2064 + (kg + (l16 >> 3) * 8) * 2));
                    mma16816(acc, af, bf2);
                }
                __syncthreads();
            }

            #pragma unroll
            for (int half = 0; half < 2; half++) {
                int row = r0 + half * 8;
                float ch0 = acc[half * 2 + 0], ch1 = acc[half * 2 + 1];
                float z0 = acv[0] * cxv[half].x * ch0 + b1cv[0] * cxv[half].x + b2cv[0] * ch0 + bcvv[0];
                float z1 = acv[1] * cxv[half].y * ch1 + b1cv[1] * cxv[half].y + b2cv[1] * ch1 + bcvv[1];
                float c0 = tanhf(z0), c1 = tanhf(z1);
                float hn0 = ur[half][0] * hvp[half].x + (1.f - ur[half][0]) * c0;
                float hn1 = ur[half][1] * hvp[half].y + (1.f - ur[half][1]) * c1;
                __stcg((float2*)(g_h + (size_t)row * 1024 + col0 + ecol), make_float2(hn0, hn1));
                __nv_bfloat162 p = __floats2bfloat162_rn(hn0, hn1);
                __stcg((uint32_t*)(g_hb + (size_t)row * 1024 + col0 + ecol), *(uint32_t*)&p);
                size_t off = (size_t)t * BD * HD + (size_t)row * HD + col0 + ecol;
                *(float2*)(outF + off) = make_float2(hn0, hn1);
                *(__nv_bfloat162*)(outB + off) = p;
            }
        }
        bar++; gsync(bar * nCTA);
    }
}

// ---------------- NCE ----------------
__global__ __launch_bounds__(256)
void k_nce_samp(float* __restrict__ outsum)
{
    __shared__ float As[8][132];
    __shared__ float Bs[8][64];
    __shared__ float red[256];
    const int tid = threadIdx.x;
    const int rowBase = blockIdx.x * 128;

    const int arow = tid >> 1;
    const int acol = (tid & 1) << 2;
    int gi = rowBase + arow;
    size_t aoff = (size_t)((gi & 255) * BD + (gi >> 8)) * HD;

    const int brow = tid >> 5;
    const int bcl  = (tid & 31) << 1;
    const int ty = tid >> 4;
    const int tx = tid & 15;

    float acc[8][4];
    #pragma unroll
    for (int i = 0; i < 8; i++)
        #pragma unroll
        for (int j = 0; j < 4; j++) acc[i][j] = 0.f;

    for (int k0 = 0; k0 < HD; k0 += 8) {
        float4 av = *(const float4*)(g_O1 + aoff + k0 + acol);
        As[acol + 0][arow] = av.x;
        As[acol + 1][arow] = av.y;
        As[acol + 2][arow] = av.z;
        As[acol + 3][arow] = av.w;
        float2 bw = *(const float2*)(g_sampWT + (size_t)(k0 + brow) * SD + bcl);
        Bs[brow][bcl]     = bw.x;
        Bs[brow][bcl + 1] = bw.y;
        __syncthreads();
        #pragma unroll
        for (int k = 0; k < 8; k++) {
            float ar[8], br[4];
            *(float4*)&ar[0] = *(const float4*)&As[k][ty * 8];
            *(float4*)&ar[4] = *(const float4*)&As[k][ty * 8 + 4];
            *(float4*)&br[0] = *(const float4*)&Bs[k][tx * 4];
            #pragma unroll
            for (int i = 0; i < 8; i++)
                #pragma unroll
                for (int j = 0; j < 4; j++)
                    acc[i][j] += ar[i] * br[j];
        }
        __syncthreads();
    }

    float s = 0.f;
    #pragma unroll
    for (int j = 0; j < 4; j++) {
        float sbv = g_sampB[tx * 4 + j];
        #pragma unroll
        for (int i = 0; i < 8; i++)
            s += softplusf(acc[i][j] + sbv);
    }
    red[tid] = s;
    __syncthreads();
    for (int o = 128; o > 0; o >>= 1) {
        if (tid < o) red[tid] += red[tid + o];
        __syncthreads();
    }
    if (tid == 0) atomicAdd(outsum, red[0] * (1.f / 32768.f));
}

__global__ __launch_bounds__(256)
void k_nce_true(const int* __restrict__ targets, const float* __restrict__ sw,
                const float* __restrict__ sb, float* __restrict__ outsum)
{
    __shared__ float red[8];
    const int warp = threadIdx.x >> 5;
    const int lane = threadIdx.x & 31;
    const int i = blockIdx.x * 8 + warp;
    const int label = targets[i];
    const float* orow = g_O1 + (size_t)((i & 255) * BD + (i >> 8)) * HD;
    const float* wrow = sw + (size_t)label * HD;

    float s = 0.f;
    #pragma unroll
    for (int k0 = 0; k0 < HD; k0 += 128) {
        float4 a = *(const float4*)(orow + k0 + lane * 4);
        float4 w = *(const float4*)(wrow + k0 + lane * 4);
        s += a.x * w.x + a.y * w.y + a.z * w.z + a.w * w.w;
    }
    #pragma unroll
    for (int o = 16; o > 0; o >>= 1) s += __shfl_xor_sync(0xffffffffu, s, o);
    if (lane == 0) {
        float logit = s + sb[label];
        red[warp] = softplusf(-logit);
    }
    __syncthreads();
    if (threadIdx.x == 0) {
        float t = 0.f;
        #pragma unroll
        for (int w = 0; w < 8; w++) t += red[w];
        atomicAdd(outsum, t * (1.f / 32768.f));
    }
}

// ---------------- launch ----------------
extern "C" void kernel_launch(void* const* d_in, const int* in_sizes, int n_in,
                              void* d_out, int out_size)
{
    const int*   input_data = (const int*)  d_in[0];
    const int*   targets    = (const int*)  d_in[1];
    const int*   nce        = (const int*)  d_in[2];
    const float* embedding  = (const float*)d_in[3];
    const float* win        = (const float*)d_in[4];
    const float* bin_       = (const float*)d_in[5];
    const float* Wxg        = (const float*)d_in[6];
    const float* Whg        = (const float*)d_in[7];
    const float* ag         = (const float*)d_in[8];
    const float* b1g        = (const float*)d_in[9];
    const float* b2g        = (const float*)d_in[10];
    const float* bg         = (const float*)d_in[11];
    const float* Wxc        = (const float*)d_in[12];
    const float* Whc        = (const float*)d_in[13];
    const float* ac         = (const float*)d_in[14];
    const float* b1c        = (const float*)d_in[15];
    const float* b2c        = (const float*)d_in[16];
    const float* bc         = (const float*)d_in[17];
    const float* softmax_w  = (const float*)d_in[18];
    const float* softmax_b  = (const float*)d_in[19];
    float* out = (float*)d_out;

    float *pXGC, *pO1, *pO0f;
    int* pidx;
    __nv_bfloat16 *pAb, *pEb, *pWbTw, *pWbT0, *pWbT1, *pO0b;
    cudaGetSymbolAddress((void**)&pXGC, g_XGC);
    cudaGetSymbolAddress((void**)&pO1,  g_O1);
    cudaGetSymbolAddress((void**)&pO0f, g_O0f);
    cudaGetSymbolAddress((void**)&pO0b, g_O0b);
    cudaGetSymbolAddress((void**)&pidx, g_rowidx);
    cudaGetSymbolAddress((void**)&pAb,  g_Ab);
    cudaGetSymbolAddress((void**)&pEb,  g_Eb);
    cudaGetSymbolAddress((void**)&pWbTw, g_WbTw);
    cudaGetSymbolAddress((void**)&pWbT0, g_WbT0);
    cudaGetSymbolAddress((void**)&pWbT1, g_WbT1);

    cudaFuncSetAttribute(k_layerX,
                         cudaFuncAttributeMaxDynamicSharedMemorySize, 188800);

    // launch 0: setup + embedding->bf16 + all weight transposes
    k_convW<<<128 + 16384 + 1024 + 3072 + 3072, 256>>>(
        input_data, out, out_size, embedding, win, Wxg, Wxc);

    // launch 1: X(bf16) = gather(Eb) @ win + bin_   -> g_Ab directly
    k_mgemm<true, true, true><<<dim3(HD / 128, TB / 128), 256>>>(
        pEb, pWbTw, bin_, nullptr, pAb, HD, pidx);

    // launch 2: XGC = Ab @ [Wxg0|Wxc0]
    k_mgemm<false, false, false><<<dim3(NG / 128, TB / 128), 256>>>(
        pAb, pWbT0, nullptr, pXGC, nullptr, NG, nullptr);

    // launch 3: layer-0 recurrence  (ncu capture target)
    k_layerX<<<128, 256, 188800>>>(
        Whg, Whc, pXGC,
        ag, b1g, b2g, bg, ac, b1c, b2c, bc,
        pO0f, pO0b, 0u);

    // launch 4: XGC = O0b @ [Wxg1|Wxc1]
    k_mgemm<false, false, false><<<dim3(NG / 128, TB / 128), 256>>>(
        pO0b, pWbT1, nullptr, pXGC, nullptr, NG, nullptr);

    // launch 5: layer-1 recurrence -> O1 fp32 (+ unused bf16)
    k_layerX<<<128, 256, 188800>>>(
        Whg + (size_t)HD * H2, Whc + (size_t)HD * HD, pXGC,
        ag + H2, b1g + H2, b2g + H2, bg + H2,
        ac + HD, b1c + HD, b2c + HD, bc + HD,
        pO1, pO0b, 1u + 2u * TD);

    // NCE
    k_gather_samp<<<SD, 256>>>(nce, softmax_w, softmax_b);
    k_nce_true<<<TB / 8, 256>>>(targets, softmax_w, softmax_b, out);
    k_nce_samp<<<TB / 128, 256>>>(out);
}